// round 12
// baseline (speedup 1.0000x reference)
#include <cuda_runtime.h>
#include <cuda_bf16.h>
#include <math.h>
#include <stdint.h>

// Problem constants
#define NN   10000
#define EE   150000
#define FF0  128
#define HH   8
#define DD   64
#define HD   512
#define GG   64
#define CC   10
#define XCW  2048
#define ECAP 96

// ---------------- device scratch ----------------
__device__ float g_h [(size_t)NN*HD];
__device__ float g_x0[(size_t)NN*HD];
__device__ float g_xc[(size_t)NN*XCW];
__device__ float g_es[(size_t)NN*HH];
__device__ float g_ed[(size_t)NN*HH];
__device__ float g_pool[GG*XCW];
__device__ float g_z  [GG*HD];
__device__ int   g_cnt[NN];
__device__ int   g_cur[NN];
__device__ int   g_rowptr[NN+1];
__device__ int   g_csr[EE];
__device__ int   g_goff[GG+1];
// bf16x3-split operands
__device__ __nv_bfloat16 g_ab [(size_t)NN*1536];   // A'' = [hi | lo | hi]
__device__ __nv_bfloat16 g_bb0[(size_t)HD*384];    // W0'' (K=128 -> 384)
__device__ __nv_bfloat16 g_bb1[(size_t)HD*1536];
__device__ __nv_bfloat16 g_bb2[(size_t)HD*1536];
__device__ __nv_bfloat16 g_bb3[(size_t)HD*1536];

// ---------------- small utility kernels ----------------
__global__ void fill2_kernel(int* a, int* b, int n) {
    int i = blockIdx.x * blockDim.x + threadIdx.x;
    if (i < n) { a[i] = 0; b[i] = 0; }
}

__global__ void fill_int_kernel(int* p, int v, int n) {
    int i = blockIdx.x * blockDim.x + threadIdx.x;
    if (i < n) p[i] = v;
}

__global__ void hist_kernel(const int* __restrict__ dst, int* __restrict__ cnt) {
    int i = blockIdx.x * blockDim.x + threadIdx.x;
    if (i < EE) atomicAdd(&cnt[dst[i]], 1);
}

__global__ void scan_kernel(const int* __restrict__ cnt, int* __restrict__ rowptr) {
    __shared__ int sums[1024];
    int t = threadIdx.x;
    int base = t * 10;
    int loc[10];
    int s = 0;
#pragma unroll
    for (int i = 0; i < 10; i++) {
        loc[i] = s;
        int idx = base + i;
        s += (idx < NN) ? cnt[idx] : 0;
    }
    int tot = s;
    sums[t] = s;
    __syncthreads();
    for (int off = 1; off < 1024; off <<= 1) {
        int v = (t >= off) ? sums[t - off] : 0;
        __syncthreads();
        sums[t] += v;
        __syncthreads();
    }
    int excl = sums[t] - tot;
#pragma unroll
    for (int i = 0; i < 10; i++) {
        int idx = base + i;
        if (idx < NN) rowptr[idx] = excl + loc[i];
    }
    if (t == 1023) rowptr[NN] = sums[1023];
}

__global__ void scatter_kernel(const int* __restrict__ src, const int* __restrict__ dst,
                               const int* __restrict__ rowptr, int* __restrict__ cur,
                               int* __restrict__ csr) {
    int i = blockIdx.x * blockDim.x + threadIdx.x;
    if (i >= EE) return;
    int d = dst[i];
    int pos = atomicAdd(&cur[d], 1);
    csr[rowptr[d] + pos] = src[i];
}

__global__ void goff_min_kernel(const int* __restrict__ batch, int* __restrict__ goff) {
    int i = blockIdx.x * blockDim.x + threadIdx.x;
    if (i < NN) atomicMin(&goff[batch[i]], i);
}

__global__ void goff_fix_kernel(int* goff) {
    goff[GG] = NN;
    for (int g = GG - 1; g >= 0; g--)
        if (goff[g] > goff[g + 1]) goff[g] = goff[g + 1];
}

// ---------------- bf16x3 split prep ----------------
__device__ __forceinline__ uint32_t pack_bf2(float a, float b) {
    __nv_bfloat162 t = __floats2bfloat162_rn(a, b);
    return *(uint32_t*)&t;
}

__global__ void aprep_kernel(const float* __restrict__ in, int lda, int K,
                             __nv_bfloat16* __restrict__ out) {
    int half = K >> 1;
    int idx = blockIdx.x * 256 + threadIdx.x;
    if (idx >= NN * half) return;
    int m  = idx / half;
    int kk = (idx - m * half) * 2;
    float2 v = *(const float2*)&in[(size_t)m * lda + kk];
    float hx = __bfloat162float(__float2bfloat16(v.x));
    float hy = __bfloat162float(__float2bfloat16(v.y));
    uint32_t hi = pack_bf2(hx, hy);
    uint32_t lo = pack_bf2(v.x - hx, v.y - hy);
    size_t base = (size_t)m * (3 * K) + kk;
    *(uint32_t*)&out[base]         = hi;
    *(uint32_t*)&out[base + K]     = lo;
    *(uint32_t*)&out[base + 2 * K] = hi;
}

__device__ __forceinline__ void bprep_one(const float* __restrict__ W, int K,
                                          __nv_bfloat16* __restrict__ out, int idx) {
    int half = K >> 1;
    int n  = idx / half;
    int kk = (idx - n * half) * 2;
    float v0 = W[(size_t)kk * HD + n];
    float v1 = W[(size_t)(kk + 1) * HD + n];
    float h0 = __bfloat162float(__float2bfloat16(v0));
    float h1 = __bfloat162float(__float2bfloat16(v1));
    uint32_t hi = pack_bf2(h0, h1);
    uint32_t lo = pack_bf2(v0 - h0, v1 - h1);
    size_t base = (size_t)n * (3 * K) + kk;
    *(uint32_t*)&out[base]         = hi;
    *(uint32_t*)&out[base + K]     = hi;
    *(uint32_t*)&out[base + 2 * K] = lo;
}

__global__ void bprep_all_kernel(const float* __restrict__ W0, const float* __restrict__ W1,
                                 const float* __restrict__ W2, const float* __restrict__ W3,
                                 __nv_bfloat16* b0, __nv_bfloat16* b1,
                                 __nv_bfloat16* b2, __nv_bfloat16* b3) {
    const int t0 = HD * (FF0 / 2);
    const int t1 = HD * (HD / 2);
    int idx = blockIdx.x * 256 + threadIdx.x;
    if (idx < t0) { bprep_one(W0, FF0, b0, idx); return; }
    idx -= t0;
    if (idx < t1) { bprep_one(W1, HD, b1, idx); return; }
    idx -= t1;
    if (idx < t1) { bprep_one(W2, HD, b2, idx); return; }
    idx -= t1;
    if (idx < t1) { bprep_one(W3, HD, b3, idx); }
}

// ---------------- bf16 mma GEMM: 512 thr, tile 128x256, 4-stage cp.async ----------
#define BK    32
#define LDP   40
#define STAGES 4
#define A_STAGE (128 * LDP)
#define B_STAGE (256 * LDP)
#define GEMM_SMEM (STAGES * (A_STAGE + B_STAGE) * 2)   // 122880 B

__device__ __forceinline__ uint32_t s2u(const void* p) {
    return (uint32_t)__cvta_generic_to_shared(p);
}

__global__ __launch_bounds__(512, 1)
void gemm_bf16(const __nv_bfloat16* __restrict__ A,   // [M][K3]
               const __nv_bfloat16* __restrict__ Bm,  // [512][K3]
               float* __restrict__ C, int M, int K3) {
    extern __shared__ __nv_bfloat16 smem[];
    __nv_bfloat16* As = smem;                             // [STAGES][128*LDP]
    __nv_bfloat16* Bs = smem + STAGES * A_STAGE;          // [STAGES][256*LDP]

    const int tid  = threadIdx.x;
    const int lane = tid & 31;
    const int wid  = tid >> 5;          // 0..15
    const int wm   = (wid & 3) * 32;    // 4 m-groups
    const int wn   = (wid >> 2) * 64;   // 4 n-groups (N=256)
    const int bx   = blockIdx.x;        // 0..1 (N halves of 512)
    const int by   = blockIdx.y;        // M block

    const int nchunks = K3 / BK;
    const int r0l = tid >> 2;           // 0..127
    const int seg = (tid & 3) * 8;

    float acc[2][8][4];
#pragma unroll
    for (int mt = 0; mt < 2; mt++)
#pragma unroll
        for (int nt = 0; nt < 8; nt++)
#pragma unroll
            for (int q = 0; q < 4; q++) acc[mt][nt][q] = 0.f;

    auto load_stage = [&](int c, int buf) {
        const __nv_bfloat16* Ac = A + c * BK;
        const __nv_bfloat16* Bc = Bm + c * BK;
        __nv_bfloat16* Asb = As + buf * A_STAGE;
        __nv_bfloat16* Bsb = Bs + buf * B_STAGE;
        {   // A: 128 rows, one per thread-quad
            int r  = r0l;
            int gr = by * 128 + r;
            int grc = gr < M ? gr : M - 1;
            uint32_t sa = s2u(&Asb[r * LDP + seg]);
            const void* ga = Ac + (size_t)grc * K3 + seg;
            int sz = (gr < M) ? 16 : 0;
            asm volatile("cp.async.cg.shared.global [%0], [%1], 16, %2;"
                         :: "r"(sa), "l"(ga), "r"(sz));
        }
#pragma unroll
        for (int i = 0; i < 2; i++) {   // B: 256 rows
            int r  = r0l + i * 128;
            int gn = bx * 256 + r;
            uint32_t sb = s2u(&Bsb[r * LDP + seg]);
            const void* gb = Bc + (size_t)gn * K3 + seg;
            asm volatile("cp.async.cg.shared.global [%0], [%1], 16;"
                         :: "r"(sb), "l"(gb));
        }
        asm volatile("cp.async.commit_group;");
    };

    int pre = nchunks < (STAGES - 1) ? nchunks : (STAGES - 1);
    for (int s = 0; s < pre; s++) load_stage(s, s);

    for (int c = 0; c < nchunks; c++) {
        asm volatile("cp.async.wait_group %0;" :: "n"(STAGES - 2));
        __syncthreads();
        if (c + STAGES - 1 < nchunks) load_stage(c + STAGES - 1, (c + STAGES - 1) & (STAGES - 1));

        int buf = c & (STAGES - 1);
        const __nv_bfloat16* Asb = As + buf * A_STAGE;
        const __nv_bfloat16* Bsb = Bs + buf * B_STAGE;

#pragma unroll
        for (int kk = 0; kk < BK; kk += 16) {
            uint32_t a[2][4];
#pragma unroll
            for (int mt = 0; mt < 2; mt++) {
                int row = wm + mt * 16 + (lane & 15);
                uint32_t addr = s2u(&Asb[row * LDP + kk + ((lane >> 4) << 3)]);
                asm volatile("ldmatrix.sync.aligned.m8n8.x4.shared.b16 {%0,%1,%2,%3}, [%4];"
                             : "=r"(a[mt][0]), "=r"(a[mt][1]), "=r"(a[mt][2]), "=r"(a[mt][3])
                             : "r"(addr));
            }
            uint32_t b[8][2];
#pragma unroll
            for (int p = 0; p < 4; p++) {
                int row = wn + p * 16 + ((lane >> 4) << 3) + (lane & 7);
                uint32_t addr = s2u(&Bsb[row * LDP + kk + (((lane >> 3) & 1) << 3)]);
                uint32_t r0, r1, r2, r3;
                asm volatile("ldmatrix.sync.aligned.m8n8.x4.shared.b16 {%0,%1,%2,%3}, [%4];"
                             : "=r"(r0), "=r"(r1), "=r"(r2), "=r"(r3) : "r"(addr));
                b[2 * p][0] = r0; b[2 * p][1] = r1;
                b[2 * p + 1][0] = r2; b[2 * p + 1][1] = r3;
            }
#pragma unroll
            for (int nt = 0; nt < 8; nt++)
#pragma unroll
                for (int mt = 0; mt < 2; mt++) {
                    asm volatile(
                        "mma.sync.aligned.m16n8k16.row.col.f32.bf16.bf16.f32 "
                        "{%0,%1,%2,%3}, {%4,%5,%6,%7}, {%8,%9}, {%0,%1,%2,%3};"
                        : "+f"(acc[mt][nt][0]), "+f"(acc[mt][nt][1]),
                          "+f"(acc[mt][nt][2]), "+f"(acc[mt][nt][3])
                        : "r"(a[mt][0]), "r"(a[mt][1]), "r"(a[mt][2]), "r"(a[mt][3]),
                          "r"(b[nt][0]), "r"(b[nt][1]));
                }
        }
    }

#pragma unroll
    for (int mt = 0; mt < 2; mt++) {
        int row0 = by * 128 + wm + mt * 16 + (lane >> 2);
#pragma unroll
        for (int nt = 0; nt < 8; nt++) {
            int col = bx * 256 + wn + nt * 8 + (lane & 3) * 2;
            if (row0 < M)
                *(float2*)&C[(size_t)row0 * HD + col] =
                    make_float2(acc[mt][nt][0], acc[mt][nt][1]);
            if (row0 + 8 < M)
                *(float2*)&C[(size_t)(row0 + 8) * HD + col] =
                    make_float2(acc[mt][nt][2], acc[mt][nt][3]);
        }
    }
}

// ---------------- per-node attention scores ----------------
__global__ __launch_bounds__(256)
void attn_score_kernel(const float* __restrict__ hmat,
                       const float* __restrict__ a_src,
                       const float* __restrict__ a_dst,
                       float* __restrict__ es, float* __restrict__ ed) {
    int n = blockIdx.x;
    int w = threadIdx.x >> 5, lane = threadIdx.x & 31;
    float2 hv = *(const float2*)&hmat[(size_t)n * HD + w * DD + lane * 2];
    float2 av = *(const float2*)&a_src[w * DD + lane * 2];
    float2 bv = *(const float2*)&a_dst[w * DD + lane * 2];
    float s = hv.x * av.x + hv.y * av.y;
    float d = hv.x * bv.x + hv.y * bv.y;
#pragma unroll
    for (int o = 16; o; o >>= 1) {
        s += __shfl_down_sync(0xffffffffu, s, o);
        d += __shfl_down_sync(0xffffffffu, d, o);
    }
    if (lane == 0) {
        es[(size_t)n * HH + w] = s;
        ed[(size_t)n * HH + w] = d;
    }
}

// ---------------- fused GAT aggregation (+ optional bf16x3 emit) ----------------
__global__ __launch_bounds__(128)
void gat_agg_kernel(const float* __restrict__ hmat,
                    const int* __restrict__ csr,
                    const int* __restrict__ rowptr,
                    const float* __restrict__ es,
                    const float* __restrict__ ed,
                    const float* __restrict__ bias,
                    float* __restrict__ out, int ostride,
                    __nv_bfloat16* __restrict__ asplit) {
    int n = blockIdx.x;
    int t = threadIdx.x;
    int beg = rowptr[n], end = rowptr[n + 1];
    int deg = end - beg;

    __shared__ float edn[8];
    __shared__ float red[16][8];
    __shared__ float mden[16];
    __shared__ int   ssh[ECAP];
    __shared__ float esh[ECAP][8];

    if (t < 8) edn[t] = ed[(size_t)n * HH + t];
    for (int j = t; j < deg && j < ECAP; j += 128) ssh[j] = csr[beg + j];
    __syncthreads();

    int hh  = t & 7;
    int l16 = t >> 3;

    float mx = -INFINITY;
    for (int j = l16; j < deg; j += 16) {
        int s = (j < ECAP) ? ssh[j] : csr[beg + j];
        float e = es[(size_t)s * HH + hh] + edn[hh];
        e = e > 0.f ? e : 0.01f * e;
        if (j < ECAP) esh[j][hh] = e;
        mx = fmaxf(mx, e);
    }
    red[l16][hh] = mx;
    __syncthreads();
    if (t < 8) {
        float v = -INFINITY;
#pragma unroll
        for (int i = 0; i < 16; i++) v = fmaxf(v, red[i][t]);
        mden[t] = v;
    }
    __syncthreads();
    float m_h = mden[hh];

    float sm = 0.f;
    for (int j = l16; j < deg; j += 16) {
        float e;
        if (j < ECAP) e = esh[j][hh];
        else {
            int s = csr[beg + j];
            e = es[(size_t)s * HH + hh] + edn[hh];
            e = e > 0.f ? e : 0.01f * e;
        }
        float ex = __expf(e - m_h);
        if (j < ECAP) esh[j][hh] = ex;
        sm += ex;
    }
    red[l16][hh] = sm;
    __syncthreads();
    if (t < 8) {
        float v = 0.f;
#pragma unroll
        for (int i = 0; i < 16; i++) v += red[i][t];
        mden[8 + t] = 1.f / v;
    }
    __syncthreads();

    int hd = t >> 4;
    float invd = mden[8 + hd];
    float mh2  = mden[hd];
    int col = t * 4;
    float a0 = 0.f, a1 = 0.f, a2 = 0.f, a3 = 0.f;
#pragma unroll 2
    for (int j = 0; j < deg; j++) {
        int s; float ex;
        if (j < ECAP) { s = ssh[j]; ex = esh[j][hd]; }
        else {
            s = csr[beg + j];
            float e = es[(size_t)s * HH + hd] + edn[hd];
            e = e > 0.f ? e : 0.01f * e;
            ex = __expf(e - mh2);
        }
        float att = ex * invd;
        float4 hv = *(const float4*)&hmat[(size_t)s * HD + col];
        a0 += hv.x * att; a1 += hv.y * att; a2 += hv.z * att; a3 += hv.w * att;
    }
    float v0 = a0 + bias[col + 0];
    float v1 = a1 + bias[col + 1];
    float v2 = a2 + bias[col + 2];
    float v3 = a3 + bias[col + 3];
    float4 o;
    o.x = v0 > 0.f ? v0 : expm1f(v0);
    o.y = v1 > 0.f ? v1 : expm1f(v1);
    o.z = v2 > 0.f ? v2 : expm1f(v2);
    o.w = v3 > 0.f ? v3 : expm1f(v3);
    *(float4*)&out[(size_t)n * ostride + col] = o;

    if (asplit) {
        float h0 = __bfloat162float(__float2bfloat16(o.x));
        float h1 = __bfloat162float(__float2bfloat16(o.y));
        float h2 = __bfloat162float(__float2bfloat16(o.z));
        float h3 = __bfloat162float(__float2bfloat16(o.w));
        uint32_t hi01 = pack_bf2(h0, h1), hi23 = pack_bf2(h2, h3);
        uint32_t lo01 = pack_bf2(o.x - h0, o.y - h1);
        uint32_t lo23 = pack_bf2(o.z - h2, o.w - h3);
        size_t base = (size_t)n * 1536 + col;
        *(uint32_t*)&asplit[base]            = hi01;
        *(uint32_t*)&asplit[base + 2]        = hi23;
        *(uint32_t*)&asplit[base + 512]      = lo01;
        *(uint32_t*)&asplit[base + 514]      = lo23;
        *(uint32_t*)&asplit[base + 1024]     = hi01;
        *(uint32_t*)&asplit[base + 1026]     = hi23;
    }
}

// ---------------- residual ----------------
__global__ void resid_kernel(const float* __restrict__ x0, float* __restrict__ xc,
                             __nv_bfloat16* __restrict__ asplit) {
    int i = blockIdx.x * blockDim.x + threadIdx.x;
    if (i >= NN * HD) return;
    int n = i >> 9, j = i & 511;
    float v = x0[i] + xc[(size_t)n * XCW + 1024 + j];
    xc[(size_t)n * XCW + 1536 + j] = v;
    __nv_bfloat16 hb = __float2bfloat16(v);
    float hf = __bfloat162float(hb);
    size_t base = (size_t)n * 1536 + j;
    asplit[base]        = hb;
    asplit[base + 512]  = __float2bfloat16(v - hf);
    asplit[base + 1024] = hb;
}

// ---------------- pooling ----------------
__global__ void pool_kernel(const float* __restrict__ xc, const int* __restrict__ goff,
                            float* __restrict__ pooled) {
    int g = blockIdx.y;
    int col = blockIdx.x * 128 + threadIdx.x;
    int beg = goff[g], end = goff[g + 1];
    float v = -INFINITY;
    for (int n = beg; n < end; n++)
        v = fmaxf(v, xc[(size_t)n * XCW + col]);
    if (!isfinite(v)) v = 0.f;
    pooled[g * XCW + col] = v;
}

// ---------------- MLP layer 1 (pooled rows cached in smem) ----------------
__global__ __launch_bounds__(128)
void mlp1_kernel(const float* __restrict__ pooled, const float* __restrict__ mW1,
                 const float* __restrict__ mb1, float* __restrict__ z) {
    __shared__ float ps[4][XCW];
    int j  = blockIdx.x * 128 + threadIdx.x;
    int g0 = blockIdx.y * 4;
#pragma unroll
    for (int gg = 0; gg < 4; gg++)
        for (int k = threadIdx.x; k < XCW; k += 128)
            ps[gg][k] = pooled[(g0 + gg) * XCW + k];
    __syncthreads();
    float acc[4];
#pragma unroll
    for (int gg = 0; gg < 4; gg++) acc[gg] = 0.f;
#pragma unroll 4
    for (int k = 0; k < XCW; k++) {
        float w = mW1[(size_t)k * HD + j];
#pragma unroll
        for (int gg = 0; gg < 4; gg++)
            acc[gg] += ps[gg][k] * w;
    }
    float bb = mb1[j];
#pragma unroll
    for (int gg = 0; gg < 4; gg++)
        z[(g0 + gg) * HD + j] = acc[gg] + bb;
}

// ---------------- BatchNorm + ReLU ----------------
__global__ void bn_relu_kernel(float* __restrict__ z, const float* __restrict__ gamma,
                               const float* __restrict__ beta) {
    int j = blockIdx.x;
    int t = threadIdx.x;
    __shared__ float part[2];
    float v = z[t * HD + j];
    float s = v;
#pragma unroll
    for (int o = 16; o; o >>= 1) s += __shfl_down_sync(0xffffffffu, s, o);
    if ((t & 31) == 0) part[t >> 5] = s;
    __syncthreads();
    float mu = (part[0] + part[1]) * (1.f / 64.f);
    __syncthreads();
    float dv = v - mu;
    float s2 = dv * dv;
#pragma unroll
    for (int o = 16; o; o >>= 1) s2 += __shfl_down_sync(0xffffffffu, s2, o);
    if ((t & 31) == 0) part[t >> 5] = s2;
    __syncthreads();
    float var = (part[0] + part[1]) * (1.f / 64.f);
    float norm = dv * rsqrtf(var + 1e-5f) * gamma[j] + beta[j];
    z[t * HD + j] = fmaxf(norm, 0.f);
}

// ---------------- final GEMM ----------------
__global__ void mlp2_kernel(const float* __restrict__ z, const float* __restrict__ mW2,
                            const float* __restrict__ mb2, float* __restrict__ out) {
    int t = threadIdx.x;
    if (t >= GG * CC) return;
    int g = t / CC, c = t % CC;
    float s = mb2[c];
    for (int k = 0; k < HD; k++) s += z[g * HD + k] * mW2[k * CC + c];
    out[t] = s;
}

// ---------------- host helpers ----------------
static void run_gemm(const __nv_bfloat16* pAB, const __nv_bfloat16* pBB,
                     float* pH, int K3) {
    dim3 grid(2, (NN + 127) / 128);
    gemm_bf16<<<grid, 512, GEMM_SMEM>>>(pAB, pBB, pH, NN, K3);
}

static void run_attn_agg(const float* pH,
                         const float* a_s, const float* a_d, const float* b,
                         float* pES, float* pED,
                         const int* pCSR, const int* pROW,
                         float* outp, int ostride, __nv_bfloat16* emit) {
    attn_score_kernel<<<NN, 256>>>(pH, a_s, a_d, pES, pED);
    gat_agg_kernel<<<NN, 128>>>(pH, pCSR, pROW, pES, pED, b, outp, ostride, emit);
}

extern "C" void kernel_launch(void* const* d_in, const int* in_sizes, int n_in,
                              void* d_out, int out_size) {
    (void)in_sizes; (void)n_in; (void)out_size;
    const float* x     = (const float*)d_in[0];
    const int*   ei    = (const int*)  d_in[1];
    const int*   batch = (const int*)  d_in[2];
    const float* W0  = (const float*)d_in[3];
    const float* as0 = (const float*)d_in[4];
    const float* ad0 = (const float*)d_in[5];
    const float* b0  = (const float*)d_in[6];
    const float* W1  = (const float*)d_in[7];
    const float* as1 = (const float*)d_in[8];
    const float* ad1 = (const float*)d_in[9];
    const float* b1  = (const float*)d_in[10];
    const float* W2  = (const float*)d_in[11];
    const float* as2 = (const float*)d_in[12];
    const float* ad2 = (const float*)d_in[13];
    const float* b2  = (const float*)d_in[14];
    const float* W3  = (const float*)d_in[15];
    const float* as3 = (const float*)d_in[16];
    const float* ad3 = (const float*)d_in[17];
    const float* b3  = (const float*)d_in[18];
    const float* mW1 = (const float*)d_in[19];
    const float* mb1 = (const float*)d_in[20];
    const float* gam = (const float*)d_in[21];
    const float* bet = (const float*)d_in[22];
    const float* mW2 = (const float*)d_in[23];
    const float* mb2 = (const float*)d_in[24];
    float* outp = (float*)d_out;

    const int* src = ei;
    const int* dst = ei + EE;

    float *pH, *pX0, *pXC, *pES, *pED, *pPOOL, *pZ;
    int *pCNT, *pCUR, *pROW, *pCSR, *pGOFF;
    __nv_bfloat16 *pAB, *pBB0, *pBB1, *pBB2, *pBB3;
    cudaGetSymbolAddress((void**)&pH,   g_h);
    cudaGetSymbolAddress((void**)&pX0,  g_x0);
    cudaGetSymbolAddress((void**)&pXC,  g_xc);
    cudaGetSymbolAddress((void**)&pES,  g_es);
    cudaGetSymbolAddress((void**)&pED,  g_ed);
    cudaGetSymbolAddress((void**)&pPOOL,g_pool);
    cudaGetSymbolAddress((void**)&pZ,   g_z);
    cudaGetSymbolAddress((void**)&pCNT, g_cnt);
    cudaGetSymbolAddress((void**)&pCUR, g_cur);
    cudaGetSymbolAddress((void**)&pROW, g_rowptr);
    cudaGetSymbolAddress((void**)&pCSR, g_csr);
    cudaGetSymbolAddress((void**)&pGOFF,g_goff);
    cudaGetSymbolAddress((void**)&pAB,  g_ab);
    cudaGetSymbolAddress((void**)&pBB0, g_bb0);
    cudaGetSymbolAddress((void**)&pBB1, g_bb1);
    cudaGetSymbolAddress((void**)&pBB2, g_bb2);
    cudaGetSymbolAddress((void**)&pBB3, g_bb3);

    cudaFuncSetAttribute(gemm_bf16, cudaFuncAttributeMaxDynamicSharedMemorySize, GEMM_SMEM);

    const int bprep_total = HD * (FF0 / 2) + 3 * HD * (HD / 2);

    // Launch order: gemm_bf16 is launch #4 (ncu sample position).
    aprep_kernel<<<(NN * (FF0 / 2) + 255) / 256, 256>>>(x, FF0, FF0, pAB);   // 1
    bprep_all_kernel<<<(bprep_total + 255) / 256, 256>>>(W0, W1, W2, W3,
                                                         pBB0, pBB1, pBB2, pBB3); // 2
    fill2_kernel<<<(NN + 255) / 256, 256>>>(pCNT, pCUR, NN);                 // 3
    run_gemm(pAB, pBB0, pH, 3 * FF0);                                        // 4 <-- profiled
    hist_kernel<<<(EE + 255) / 256, 256>>>(dst, pCNT);                       // 5
    scan_kernel<<<1, 1024>>>(pCNT, pROW);                                    // 6
    scatter_kernel<<<(EE + 255) / 256, 256>>>(src, dst, pROW, pCUR, pCSR);   // 7
    run_attn_agg(pH, as0, ad0, b0, pES, pED, pCSR, pROW, pX0, HD, pAB);      // 8,9

    // Layer 1 (head)
    run_gemm(pAB, pBB1, pH, 3 * HD);
    run_attn_agg(pH, as1, ad1, b1, pES, pED, pCSR, pROW, pXC + 512, XCW, pAB);

    // Layer 2 (body)
    run_gemm(pAB, pBB2, pH, 3 * HD);
    run_attn_agg(pH, as2, ad2, b2, pES, pED, pCSR, pROW, pXC + 1024, XCW, nullptr);

    // Residual -> x3 (emits split), Layer 3 (tail)
    resid_kernel<<<(NN * HD + 255) / 256, 256>>>(pX0, pXC, pAB);
    run_gemm(pAB, pBB3, pH, 3 * HD);
    run_attn_agg(pH, as3, ad3, b3, pES, pED, pCSR, pROW, pXC, XCW, nullptr);

    // Graph offsets + pool + MLP head
    fill_int_kernel<<<1, GG + 1>>>(pGOFF, NN, GG + 1);
    goff_min_kernel<<<(NN + 255) / 256, 256>>>(batch, pGOFF);
    goff_fix_kernel<<<1, 1>>>(pGOFF);
    pool_kernel<<<dim3(XCW / 128, GG), 128>>>(pXC, pGOFF, pPOOL);
    mlp1_kernel<<<dim3(HD / 128, GG / 4), 128>>>(pPOOL, mW1, mb1, pZ);
    bn_relu_kernel<<<HD, 64>>>(pZ, gam, bet);
    mlp2_kernel<<<1, GG * CC>>>(pZ, mW2, mb2, outp);
}

// round 13
// speedup vs baseline: 1.1266x; 1.1266x over previous
#include <cuda_runtime.h>
#include <cuda_bf16.h>
#include <math.h>
#include <stdint.h>

// Problem constants
#define NN   10000
#define EE   150000
#define FF0  128
#define HH   8
#define DD   64
#define HD   512
#define GG   64
#define CC   10
#define XCW  2048
#define ECAP 96

// ---------------- device scratch ----------------
__device__ float g_h [(size_t)NN*HD];
__device__ float g_x0[(size_t)NN*HD];
__device__ float g_xc[(size_t)NN*XCW];
__device__ float g_es[(size_t)NN*HH];
__device__ float g_ed[(size_t)NN*HH];
__device__ float g_pool[GG*XCW];
__device__ float g_z  [GG*HD];
__device__ int   g_cnt[NN];      // zero-initialized; scan re-zeroes each run
__device__ int   g_cur[NN];      // zero-initialized; gat_agg layer0 re-zeroes
__device__ int   g_rowptr[NN+1];
__device__ int   g_csr[EE];
__device__ int   g_goff[GG+1];
// bf16x3-split operands
__device__ __nv_bfloat16 g_ab [(size_t)NN*1536];   // A'' = [hi | lo | hi]
__device__ __nv_bfloat16 g_bb0[(size_t)HD*384];    // W0'' (K=128 -> 384)
__device__ __nv_bfloat16 g_bb1[(size_t)HD*1536];
__device__ __nv_bfloat16 g_bb2[(size_t)HD*1536];
__device__ __nv_bfloat16 g_bb3[(size_t)HD*1536];

// ---------------- small utility kernels ----------------
__global__ void fill_int_kernel(int* p, int v, int n) {
    int i = blockIdx.x * blockDim.x + threadIdx.x;
    if (i < n) p[i] = v;
}

__global__ void hist_kernel(const int* __restrict__ dst, int* __restrict__ cnt) {
    int i = blockIdx.x * blockDim.x + threadIdx.x;
    if (i < EE) atomicAdd(&cnt[dst[i]], 1);
}

// single block, 1024 threads; exclusive scan of cnt into rowptr; zeroes cnt after read
__global__ void scan_kernel(int* __restrict__ cnt, int* __restrict__ rowptr) {
    __shared__ int sums[1024];
    int t = threadIdx.x;
    int base = t * 10;
    int loc[10];
    int s = 0;
#pragma unroll
    for (int i = 0; i < 10; i++) {
        loc[i] = s;
        int idx = base + i;
        if (idx < NN) { s += cnt[idx]; cnt[idx] = 0; }
    }
    int tot = s;
    sums[t] = s;
    __syncthreads();
    for (int off = 1; off < 1024; off <<= 1) {
        int v = (t >= off) ? sums[t - off] : 0;
        __syncthreads();
        sums[t] += v;
        __syncthreads();
    }
    int excl = sums[t] - tot;
#pragma unroll
    for (int i = 0; i < 10; i++) {
        int idx = base + i;
        if (idx < NN) rowptr[idx] = excl + loc[i];
    }
    if (t == 1023) rowptr[NN] = sums[1023];
}

__global__ void scatter_kernel(const int* __restrict__ src, const int* __restrict__ dst,
                               const int* __restrict__ rowptr, int* __restrict__ cur,
                               int* __restrict__ csr) {
    int i = blockIdx.x * blockDim.x + threadIdx.x;
    if (i >= EE) return;
    int d = dst[i];
    int pos = atomicAdd(&cur[d], 1);
    csr[rowptr[d] + pos] = src[i];
}

__global__ void goff_min_kernel(const int* __restrict__ batch, int* __restrict__ goff) {
    int i = blockIdx.x * blockDim.x + threadIdx.x;
    if (i < NN) atomicMin(&goff[batch[i]], i);
}

__global__ void goff_fix_kernel(int* goff) {
    goff[GG] = NN;
    for (int g = GG - 1; g >= 0; g--)
        if (goff[g] > goff[g + 1]) goff[g] = goff[g + 1];
}

// ---------------- bf16x3 split prep ----------------
__device__ __forceinline__ uint32_t pack_bf2(float a, float b) {
    __nv_bfloat162 t = __floats2bfloat162_rn(a, b);
    return *(uint32_t*)&t;
}

__global__ void aprep_kernel(const float* __restrict__ in, int lda, int K,
                             __nv_bfloat16* __restrict__ out) {
    int half = K >> 1;
    int idx = blockIdx.x * 256 + threadIdx.x;
    if (idx >= NN * half) return;
    int m  = idx / half;
    int kk = (idx - m * half) * 2;
    float2 v = *(const float2*)&in[(size_t)m * lda + kk];
    float hx = __bfloat162float(__float2bfloat16(v.x));
    float hy = __bfloat162float(__float2bfloat16(v.y));
    uint32_t hi = pack_bf2(hx, hy);
    uint32_t lo = pack_bf2(v.x - hx, v.y - hy);
    size_t base = (size_t)m * (3 * K) + kk;
    *(uint32_t*)&out[base]         = hi;
    *(uint32_t*)&out[base + K]     = lo;
    *(uint32_t*)&out[base + 2 * K] = hi;
}

__device__ __forceinline__ void bprep_one(const float* __restrict__ W, int K,
                                          __nv_bfloat16* __restrict__ out, int idx) {
    int half = K >> 1;
    int n  = idx / half;
    int kk = (idx - n * half) * 2;
    float v0 = W[(size_t)kk * HD + n];
    float v1 = W[(size_t)(kk + 1) * HD + n];
    float h0 = __bfloat162float(__float2bfloat16(v0));
    float h1 = __bfloat162float(__float2bfloat16(v1));
    uint32_t hi = pack_bf2(h0, h1);
    uint32_t lo = pack_bf2(v0 - h0, v1 - h1);
    size_t base = (size_t)n * (3 * K) + kk;
    *(uint32_t*)&out[base]         = hi;
    *(uint32_t*)&out[base + K]     = hi;
    *(uint32_t*)&out[base + 2 * K] = lo;
}

__global__ void bprep_all_kernel(const float* __restrict__ W0, const float* __restrict__ W1,
                                 const float* __restrict__ W2, const float* __restrict__ W3,
                                 __nv_bfloat16* b0, __nv_bfloat16* b1,
                                 __nv_bfloat16* b2, __nv_bfloat16* b3) {
    const int t0 = HD * (FF0 / 2);
    const int t1 = HD * (HD / 2);
    int idx = blockIdx.x * 256 + threadIdx.x;
    if (idx < t0) { bprep_one(W0, FF0, b0, idx); return; }
    idx -= t0;
    if (idx < t1) { bprep_one(W1, HD, b1, idx); return; }
    idx -= t1;
    if (idx < t1) { bprep_one(W2, HD, b2, idx); return; }
    idx -= t1;
    if (idx < t1) { bprep_one(W3, HD, b3, idx); }
}

// ---------------- bf16 mma GEMM (R11 winner): 256 thr, tile 128x128, 4-stage ------
#define BK    32
#define LDP   40
#define STAGES 4
#define STAGE_ELEMS (128 * LDP)
#define GEMM_SMEM (STAGES * STAGE_ELEMS * 2 * 2)   // 81920 B

__device__ __forceinline__ uint32_t s2u(const void* p) {
    return (uint32_t)__cvta_generic_to_shared(p);
}

__global__ __launch_bounds__(256, 2)
void gemm_bf16(const __nv_bfloat16* __restrict__ A,   // [M][K3]
               const __nv_bfloat16* __restrict__ Bm,  // [512][K3]
               float* __restrict__ C, int M, int K3) {
    extern __shared__ __nv_bfloat16 smem[];
    __nv_bfloat16* As = smem;
    __nv_bfloat16* Bs = smem + STAGES * STAGE_ELEMS;

    const int tid  = threadIdx.x;
    const int lane = tid & 31;
    const int wid  = tid >> 5;
    const int wm   = (wid & 3) * 32;
    const int wn   = (wid >> 2) * 64;
    const int bx   = blockIdx.x;
    const int by   = blockIdx.y;

    const int nchunks = K3 / BK;
    const int r0l = tid >> 2;
    const int seg = (tid & 3) * 8;

    float acc[2][8][4];
#pragma unroll
    for (int mt = 0; mt < 2; mt++)
#pragma unroll
        for (int nt = 0; nt < 8; nt++)
#pragma unroll
            for (int q = 0; q < 4; q++) acc[mt][nt][q] = 0.f;

    auto load_stage = [&](int c, int buf) {
        const __nv_bfloat16* Ac = A + c * BK;
        const __nv_bfloat16* Bc = Bm + c * BK;
        __nv_bfloat16* Asb = As + buf * STAGE_ELEMS;
        __nv_bfloat16* Bsb = Bs + buf * STAGE_ELEMS;
#pragma unroll
        for (int i = 0; i < 2; i++) {
            int r  = r0l + i * 64;
            int gr = by * 128 + r;
            int grc = gr < M ? gr : M - 1;
            uint32_t sa = s2u(&Asb[r * LDP + seg]);
            const void* ga = Ac + (size_t)grc * K3 + seg;
            int sz = (gr < M) ? 16 : 0;
            asm volatile("cp.async.cg.shared.global [%0], [%1], 16, %2;"
                         :: "r"(sa), "l"(ga), "r"(sz));
        }
#pragma unroll
        for (int i = 0; i < 2; i++) {
            int r  = r0l + i * 64;
            int gn = bx * 128 + r;
            uint32_t sb = s2u(&Bsb[r * LDP + seg]);
            const void* gb = Bc + (size_t)gn * K3 + seg;
            asm volatile("cp.async.cg.shared.global [%0], [%1], 16;"
                         :: "r"(sb), "l"(gb));
        }
        asm volatile("cp.async.commit_group;");
    };

    int pre = nchunks < (STAGES - 1) ? nchunks : (STAGES - 1);
    for (int s = 0; s < pre; s++) load_stage(s, s);

    for (int c = 0; c < nchunks; c++) {
        asm volatile("cp.async.wait_group %0;" :: "n"(STAGES - 2));
        __syncthreads();
        if (c + STAGES - 1 < nchunks) load_stage(c + STAGES - 1, (c + STAGES - 1) & (STAGES - 1));

        int buf = c & (STAGES - 1);
        const __nv_bfloat16* Asb = As + buf * STAGE_ELEMS;
        const __nv_bfloat16* Bsb = Bs + buf * STAGE_ELEMS;

#pragma unroll
        for (int kk = 0; kk < BK; kk += 16) {
            uint32_t a[2][4];
#pragma unroll
            for (int mt = 0; mt < 2; mt++) {
                int row = wm + mt * 16 + (lane & 15);
                uint32_t addr = s2u(&Asb[row * LDP + kk + ((lane >> 4) << 3)]);
                asm volatile("ldmatrix.sync.aligned.m8n8.x4.shared.b16 {%0,%1,%2,%3}, [%4];"
                             : "=r"(a[mt][0]), "=r"(a[mt][1]), "=r"(a[mt][2]), "=r"(a[mt][3])
                             : "r"(addr));
            }
            uint32_t b[8][2];
#pragma unroll
            for (int p = 0; p < 4; p++) {
                int row = wn + p * 16 + ((lane >> 4) << 3) + (lane & 7);
                uint32_t addr = s2u(&Bsb[row * LDP + kk + (((lane >> 3) & 1) << 3)]);
                uint32_t r0, r1, r2, r3;
                asm volatile("ldmatrix.sync.aligned.m8n8.x4.shared.b16 {%0,%1,%2,%3}, [%4];"
                             : "=r"(r0), "=r"(r1), "=r"(r2), "=r"(r3) : "r"(addr));
                b[2 * p][0] = r0; b[2 * p][1] = r1;
                b[2 * p + 1][0] = r2; b[2 * p + 1][1] = r3;
            }
#pragma unroll
            for (int nt = 0; nt < 8; nt++)
#pragma unroll
                for (int mt = 0; mt < 2; mt++) {
                    asm volatile(
                        "mma.sync.aligned.m16n8k16.row.col.f32.bf16.bf16.f32 "
                        "{%0,%1,%2,%3}, {%4,%5,%6,%7}, {%8,%9}, {%0,%1,%2,%3};"
                        : "+f"(acc[mt][nt][0]), "+f"(acc[mt][nt][1]),
                          "+f"(acc[mt][nt][2]), "+f"(acc[mt][nt][3])
                        : "r"(a[mt][0]), "r"(a[mt][1]), "r"(a[mt][2]), "r"(a[mt][3]),
                          "r"(b[nt][0]), "r"(b[nt][1]));
                }
        }
    }

#pragma unroll
    for (int mt = 0; mt < 2; mt++) {
        int row0 = by * 128 + wm + mt * 16 + (lane >> 2);
#pragma unroll
        for (int nt = 0; nt < 8; nt++) {
            int col = bx * 128 + wn + nt * 8 + (lane & 3) * 2;
            if (row0 < M)
                *(float2*)&C[(size_t)row0 * HD + col] =
                    make_float2(acc[mt][nt][0], acc[mt][nt][1]);
            if (row0 + 8 < M)
                *(float2*)&C[(size_t)(row0 + 8) * HD + col] =
                    make_float2(acc[mt][nt][2], acc[mt][nt][3]);
        }
    }
}

// ---------------- per-node attention scores ----------------
__global__ __launch_bounds__(256)
void attn_score_kernel(const float* __restrict__ hmat,
                       const float* __restrict__ a_src,
                       const float* __restrict__ a_dst,
                       float* __restrict__ es, float* __restrict__ ed) {
    int n = blockIdx.x;
    int w = threadIdx.x >> 5, lane = threadIdx.x & 31;
    float2 hv = *(const float2*)&hmat[(size_t)n * HD + w * DD + lane * 2];
    float2 av = *(const float2*)&a_src[w * DD + lane * 2];
    float2 bv = *(const float2*)&a_dst[w * DD + lane * 2];
    float s = hv.x * av.x + hv.y * av.y;
    float d = hv.x * bv.x + hv.y * bv.y;
#pragma unroll
    for (int o = 16; o; o >>= 1) {
        s += __shfl_down_sync(0xffffffffu, s, o);
        d += __shfl_down_sync(0xffffffffu, d, o);
    }
    if (lane == 0) {
        es[(size_t)n * HH + w] = s;
        ed[(size_t)n * HH + w] = d;
    }
}

// ---------------- fused GAT aggregation (+ optional bf16x3 emit, + cur reset) ----
__global__ __launch_bounds__(128)
void gat_agg_kernel(const float* __restrict__ hmat,
                    const int* __restrict__ csr,
                    const int* __restrict__ rowptr,
                    const float* __restrict__ es,
                    const float* __restrict__ ed,
                    const float* __restrict__ bias,
                    float* __restrict__ out, int ostride,
                    __nv_bfloat16* __restrict__ asplit,
                    int* __restrict__ cur_reset) {
    int n = blockIdx.x;
    int t = threadIdx.x;
    int beg = rowptr[n], end = rowptr[n + 1];
    int deg = end - beg;

    __shared__ float edn[8];
    __shared__ float red[16][8];
    __shared__ float mden[16];
    __shared__ int   ssh[ECAP];
    __shared__ float esh[ECAP][8];

    if (cur_reset && t == 0) cur_reset[n] = 0;   // recycle for next graph replay
    if (t < 8) edn[t] = ed[(size_t)n * HH + t];
    for (int j = t; j < deg && j < ECAP; j += 128) ssh[j] = csr[beg + j];
    __syncthreads();

    int hh  = t & 7;
    int l16 = t >> 3;

    float mx = -INFINITY;
    for (int j = l16; j < deg; j += 16) {
        int s = (j < ECAP) ? ssh[j] : csr[beg + j];
        float e = es[(size_t)s * HH + hh] + edn[hh];
        e = e > 0.f ? e : 0.01f * e;
        if (j < ECAP) esh[j][hh] = e;
        mx = fmaxf(mx, e);
    }
    red[l16][hh] = mx;
    __syncthreads();
    if (t < 8) {
        float v = -INFINITY;
#pragma unroll
        for (int i = 0; i < 16; i++) v = fmaxf(v, red[i][t]);
        mden[t] = v;
    }
    __syncthreads();
    float m_h = mden[hh];

    float sm = 0.f;
    for (int j = l16; j < deg; j += 16) {
        float e;
        if (j < ECAP) e = esh[j][hh];
        else {
            int s = csr[beg + j];
            e = es[(size_t)s * HH + hh] + edn[hh];
            e = e > 0.f ? e : 0.01f * e;
        }
        float ex = __expf(e - m_h);
        if (j < ECAP) esh[j][hh] = ex;
        sm += ex;
    }
    red[l16][hh] = sm;
    __syncthreads();
    if (t < 8) {
        float v = 0.f;
#pragma unroll
        for (int i = 0; i < 16; i++) v += red[i][t];
        mden[8 + t] = 1.f / v;
    }
    __syncthreads();

    int hd = t >> 4;
    float invd = mden[8 + hd];
    float mh2  = mden[hd];
    int col = t * 4;
    float a0 = 0.f, a1 = 0.f, a2 = 0.f, a3 = 0.f;
#pragma unroll 4
    for (int j = 0; j < deg; j++) {
        int s; float ex;
        if (j < ECAP) { s = ssh[j]; ex = esh[j][hd]; }
        else {
            s = csr[beg + j];
            float e = es[(size_t)s * HH + hd] + edn[hd];
            e = e > 0.f ? e : 0.01f * e;
            ex = __expf(e - mh2);
        }
        float att = ex * invd;
        float4 hv = *(const float4*)&hmat[(size_t)s * HD + col];
        a0 += hv.x * att; a1 += hv.y * att; a2 += hv.z * att; a3 += hv.w * att;
    }
    float v0 = a0 + bias[col + 0];
    float v1 = a1 + bias[col + 1];
    float v2 = a2 + bias[col + 2];
    float v3 = a3 + bias[col + 3];
    float4 o;
    o.x = v0 > 0.f ? v0 : expm1f(v0);
    o.y = v1 > 0.f ? v1 : expm1f(v1);
    o.z = v2 > 0.f ? v2 : expm1f(v2);
    o.w = v3 > 0.f ? v3 : expm1f(v3);
    *(float4*)&out[(size_t)n * ostride + col] = o;

    if (asplit) {
        float h0 = __bfloat162float(__float2bfloat16(o.x));
        float h1 = __bfloat162float(__float2bfloat16(o.y));
        float h2 = __bfloat162float(__float2bfloat16(o.z));
        float h3 = __bfloat162float(__float2bfloat16(o.w));
        uint32_t hi01 = pack_bf2(h0, h1), hi23 = pack_bf2(h2, h3);
        uint32_t lo01 = pack_bf2(o.x - h0, o.y - h1);
        uint32_t lo23 = pack_bf2(o.z - h2, o.w - h3);
        size_t base = (size_t)n * 1536 + col;
        *(uint32_t*)&asplit[base]            = hi01;
        *(uint32_t*)&asplit[base + 2]        = hi23;
        *(uint32_t*)&asplit[base + 512]      = lo01;
        *(uint32_t*)&asplit[base + 514]      = lo23;
        *(uint32_t*)&asplit[base + 1024]     = hi01;
        *(uint32_t*)&asplit[base + 1026]     = hi23;
    }
}

// ---------------- residual ----------------
__global__ void resid_kernel(const float* __restrict__ x0, float* __restrict__ xc,
                             __nv_bfloat16* __restrict__ asplit) {
    int i = blockIdx.x * blockDim.x + threadIdx.x;
    if (i >= NN * HD) return;
    int n = i >> 9, j = i & 511;
    float v = x0[i] + xc[(size_t)n * XCW + 1024 + j];
    xc[(size_t)n * XCW + 1536 + j] = v;
    __nv_bfloat16 hb = __float2bfloat16(v);
    float hf = __bfloat162float(hb);
    size_t base = (size_t)n * 1536 + j;
    asplit[base]        = hb;
    asplit[base + 512]  = __float2bfloat16(v - hf);
    asplit[base + 1024] = hb;
}

// ---------------- pooling ----------------
__global__ void pool_kernel(const float* __restrict__ xc, const int* __restrict__ goff,
                            float* __restrict__ pooled) {
    int g = blockIdx.y;
    int col = blockIdx.x * 128 + threadIdx.x;
    int beg = goff[g], end = goff[g + 1];
    float v = -INFINITY;
    for (int n = beg; n < end; n++)
        v = fmaxf(v, xc[(size_t)n * XCW + col]);
    if (!isfinite(v)) v = 0.f;
    pooled[g * XCW + col] = v;
}

// ---------------- MLP layer 1 (pooled rows cached in smem) ----------------
__global__ __launch_bounds__(128)
void mlp1_kernel(const float* __restrict__ pooled, const float* __restrict__ mW1,
                 const float* __restrict__ mb1, float* __restrict__ z) {
    __shared__ float ps[4][XCW];
    int j  = blockIdx.x * 128 + threadIdx.x;
    int g0 = blockIdx.y * 4;
#pragma unroll
    for (int gg = 0; gg < 4; gg++)
        for (int k = threadIdx.x; k < XCW; k += 128)
            ps[gg][k] = pooled[(g0 + gg) * XCW + k];
    __syncthreads();
    float acc[4];
#pragma unroll
    for (int gg = 0; gg < 4; gg++) acc[gg] = 0.f;
#pragma unroll 4
    for (int k = 0; k < XCW; k++) {
        float w = mW1[(size_t)k * HD + j];
#pragma unroll
        for (int gg = 0; gg < 4; gg++)
            acc[gg] += ps[gg][k] * w;
    }
    float bb = mb1[j];
#pragma unroll
    for (int gg = 0; gg < 4; gg++)
        z[(g0 + gg) * HD + j] = acc[gg] + bb;
}

// ---------------- BatchNorm + ReLU ----------------
__global__ void bn_relu_kernel(float* __restrict__ z, const float* __restrict__ gamma,
                               const float* __restrict__ beta) {
    int j = blockIdx.x;
    int t = threadIdx.x;
    __shared__ float part[2];
    float v = z[t * HD + j];
    float s = v;
#pragma unroll
    for (int o = 16; o; o >>= 1) s += __shfl_down_sync(0xffffffffu, s, o);
    if ((t & 31) == 0) part[t >> 5] = s;
    __syncthreads();
    float mu = (part[0] + part[1]) * (1.f / 64.f);
    __syncthreads();
    float dv = v - mu;
    float s2 = dv * dv;
#pragma unroll
    for (int o = 16; o; o >>= 1) s2 += __shfl_down_sync(0xffffffffu, s2, o);
    if ((t & 31) == 0) part[t >> 5] = s2;
    __syncthreads();
    float var = (part[0] + part[1]) * (1.f / 64.f);
    float norm = dv * rsqrtf(var + 1e-5f) * gamma[j] + beta[j];
    z[t * HD + j] = fmaxf(norm, 0.f);
}

// ---------------- final GEMM ----------------
__global__ void mlp2_kernel(const float* __restrict__ z, const float* __restrict__ mW2,
                            const float* __restrict__ mb2, float* __restrict__ out) {
    int t = threadIdx.x;
    if (t >= GG * CC) return;
    int g = t / CC, c = t % CC;
    float s = mb2[c];
    for (int k = 0; k < HD; k++) s += z[g * HD + k] * mW2[k * CC + c];
    out[t] = s;
}

// ---------------- host helpers ----------------
static void run_gemm(const __nv_bfloat16* pAB, const __nv_bfloat16* pBB,
                     float* pH, int K3) {
    dim3 grid(HD / 128, (NN + 127) / 128);
    gemm_bf16<<<grid, 256, GEMM_SMEM>>>(pAB, pBB, pH, NN, K3);
}

static void run_attn_agg(const float* pH,
                         const float* a_s, const float* a_d, const float* b,
                         float* pES, float* pED,
                         const int* pCSR, const int* pROW,
                         float* outp, int ostride, __nv_bfloat16* emit, int* curz) {
    attn_score_kernel<<<NN, 256>>>(pH, a_s, a_d, pES, pED);
    gat_agg_kernel<<<NN, 128>>>(pH, pCSR, pROW, pES, pED, b, outp, ostride, emit, curz);
}

extern "C" void kernel_launch(void* const* d_in, const int* in_sizes, int n_in,
                              void* d_out, int out_size) {
    (void)in_sizes; (void)n_in; (void)out_size;
    const float* x     = (const float*)d_in[0];
    const int*   ei    = (const int*)  d_in[1];
    const int*   batch = (const int*)  d_in[2];
    const float* W0  = (const float*)d_in[3];
    const float* as0 = (const float*)d_in[4];
    const float* ad0 = (const float*)d_in[5];
    const float* b0  = (const float*)d_in[6];
    const float* W1  = (const float*)d_in[7];
    const float* as1 = (const float*)d_in[8];
    const float* ad1 = (const float*)d_in[9];
    const float* b1  = (const float*)d_in[10];
    const float* W2  = (const float*)d_in[11];
    const float* as2 = (const float*)d_in[12];
    const float* ad2 = (const float*)d_in[13];
    const float* b2  = (const float*)d_in[14];
    const float* W3  = (const float*)d_in[15];
    const float* as3 = (const float*)d_in[16];
    const float* ad3 = (const float*)d_in[17];
    const float* b3  = (const float*)d_in[18];
    const float* mW1 = (const float*)d_in[19];
    const float* mb1 = (const float*)d_in[20];
    const float* gam = (const float*)d_in[21];
    const float* bet = (const float*)d_in[22];
    const float* mW2 = (const float*)d_in[23];
    const float* mb2 = (const float*)d_in[24];
    float* outp = (float*)d_out;

    const int* src = ei;
    const int* dst = ei + EE;

    float *pH, *pX0, *pXC, *pES, *pED, *pPOOL, *pZ;
    int *pCNT, *pCUR, *pROW, *pCSR, *pGOFF;
    __nv_bfloat16 *pAB, *pBB0, *pBB1, *pBB2, *pBB3;
    cudaGetSymbolAddress((void**)&pH,   g_h);
    cudaGetSymbolAddress((void**)&pX0,  g_x0);
    cudaGetSymbolAddress((void**)&pXC,  g_xc);
    cudaGetSymbolAddress((void**)&pES,  g_es);
    cudaGetSymbolAddress((void**)&pED,  g_ed);
    cudaGetSymbolAddress((void**)&pPOOL,g_pool);
    cudaGetSymbolAddress((void**)&pZ,   g_z);
    cudaGetSymbolAddress((void**)&pCNT, g_cnt);
    cudaGetSymbolAddress((void**)&pCUR, g_cur);
    cudaGetSymbolAddress((void**)&pROW, g_rowptr);
    cudaGetSymbolAddress((void**)&pCSR, g_csr);
    cudaGetSymbolAddress((void**)&pGOFF,g_goff);
    cudaGetSymbolAddress((void**)&pAB,  g_ab);
    cudaGetSymbolAddress((void**)&pBB0, g_bb0);
    cudaGetSymbolAddress((void**)&pBB1, g_bb1);
    cudaGetSymbolAddress((void**)&pBB2, g_bb2);
    cudaGetSymbolAddress((void**)&pBB3, g_bb3);

    cudaFuncSetAttribute(gemm_bf16, cudaFuncAttributeMaxDynamicSharedMemorySize, GEMM_SMEM);

    const int bprep_total = HD * (FF0 / 2) + 3 * HD * (HD / 2);

    // cnt/cur are zero on entry (static init on first run; recycled by
    // scan_kernel / gat_agg(layer0) on every subsequent run).
    aprep_kernel<<<(NN * (FF0 / 2) + 255) / 256, 256>>>(x, FF0, FF0, pAB);   // 1
    bprep_all_kernel<<<(bprep_total + 255) / 256, 256>>>(W0, W1, W2, W3,
                                                         pBB0, pBB1, pBB2, pBB3); // 2
    hist_kernel<<<(EE + 255) / 256, 256>>>(dst, pCNT);                       // 3
    run_gemm(pAB, pBB0, pH, 3 * FF0);                                        // 4 <-- profiled
    scan_kernel<<<1, 1024>>>(pCNT, pROW);                                    // 5
    scatter_kernel<<<(EE + 255) / 256, 256>>>(src, dst, pROW, pCUR, pCSR);   // 6
    run_attn_agg(pH, as0, ad0, b0, pES, pED, pCSR, pROW, pX0, HD, pAB, pCUR); // 7,8

    // Layer 1 (head)
    run_gemm(pAB, pBB1, pH, 3 * HD);
    run_attn_agg(pH, as1, ad1, b1, pES, pED, pCSR, pROW, pXC + 512, XCW, pAB, nullptr);

    // Layer 2 (body)
    run_gemm(pAB, pBB2, pH, 3 * HD);
    run_attn_agg(pH, as2, ad2, b2, pES, pED, pCSR, pROW, pXC + 1024, XCW, nullptr, nullptr);

    // Residual -> x3 (emits split), Layer 3 (tail)
    resid_kernel<<<(NN * HD + 255) / 256, 256>>>(pX0, pXC, pAB);
    run_gemm(pAB, pBB3, pH, 3 * HD);
    run_attn_agg(pH, as3, ad3, b3, pES, pED, pCSR, pROW, pXC, XCW, nullptr, nullptr);

    // Graph offsets + pool + MLP head
    fill_int_kernel<<<1, GG + 1>>>(pGOFF, NN, GG + 1);
    goff_min_kernel<<<(NN + 255) / 256, 256>>>(batch, pGOFF);
    goff_fix_kernel<<<1, 1>>>(pGOFF);
    pool_kernel<<<dim3(XCW / 128, GG), 128>>>(pXC, pGOFF, pPOOL);
    mlp1_kernel<<<dim3(HD / 128, GG / 4), 128>>>(pPOOL, mW1, mb1, pZ);
    bn_relu_kernel<<<HD, 64>>>(pZ, gam, bet);
    mlp2_kernel<<<1, GG * CC>>>(pZ, mW2, mb2, outp);
}

// round 14
// speedup vs baseline: 1.1822x; 1.0494x over previous
#include <cuda_runtime.h>
#include <cuda_bf16.h>
#include <math.h>
#include <stdint.h>

// Problem constants
#define NN   10000
#define EE   150000
#define FF0  128
#define HH   8
#define DD   64
#define HD   512
#define GG   64
#define CC   10
#define XCW  2048
#define ECAP 96

// ---------------- device scratch ----------------
__device__ float g_h [(size_t)NN*HD];
__device__ float g_x0[(size_t)NN*HD];
__device__ float g_xc[(size_t)NN*XCW];
__device__ float g_es[(size_t)NN*HH];
__device__ float g_ed[(size_t)NN*HH];
__device__ float g_pool[GG*XCW];
__device__ float g_z  [GG*HD];
__device__ int   g_cnt[NN];      // zero-initialized; scan re-zeroes each run
__device__ int   g_cur[NN];      // zero-initialized; gat_agg layer0 re-zeroes
__device__ int   g_rowptr[NN+1];
__device__ int   g_csr[EE];
// bf16x3-split operands
__device__ __nv_bfloat16 g_ab [(size_t)NN*1536];
__device__ __nv_bfloat16 g_bb0[(size_t)HD*384];
__device__ __nv_bfloat16 g_bb1[(size_t)HD*1536];
__device__ __nv_bfloat16 g_bb2[(size_t)HD*1536];
__device__ __nv_bfloat16 g_bb3[(size_t)HD*1536];

// ---------------- utility kernels ----------------
__global__ void hist_kernel(const int* __restrict__ dst, int* __restrict__ cnt) {
    int i = blockIdx.x * blockDim.x + threadIdx.x;
    if (i < EE) atomicAdd(&cnt[dst[i]], 1);
}

// single block, 1024 threads; exclusive scan of cnt into rowptr; zeroes cnt after read
__global__ void scan_kernel(int* __restrict__ cnt, int* __restrict__ rowptr) {
    __shared__ int sums[1024];
    int t = threadIdx.x;
    int base = t * 10;
    int loc[10];
    int s = 0;
#pragma unroll
    for (int i = 0; i < 10; i++) {
        loc[i] = s;
        int idx = base + i;
        if (idx < NN) { s += cnt[idx]; cnt[idx] = 0; }
    }
    int tot = s;
    sums[t] = s;
    __syncthreads();
    for (int off = 1; off < 1024; off <<= 1) {
        int v = (t >= off) ? sums[t - off] : 0;
        __syncthreads();
        sums[t] += v;
        __syncthreads();
    }
    int excl = sums[t] - tot;
#pragma unroll
    for (int i = 0; i < 10; i++) {
        int idx = base + i;
        if (idx < NN) rowptr[idx] = excl + loc[i];
    }
    if (t == 1023) rowptr[NN] = sums[1023];
}

__global__ void scatter_kernel(const int* __restrict__ src, const int* __restrict__ dst,
                               const int* __restrict__ rowptr, int* __restrict__ cur,
                               int* __restrict__ csr) {
    int i = blockIdx.x * blockDim.x + threadIdx.x;
    if (i >= EE) return;
    int d = dst[i];
    int pos = atomicAdd(&cur[d], 1);
    csr[rowptr[d] + pos] = src[i];
}

// ---------------- bf16x3 split prep ----------------
__device__ __forceinline__ uint32_t pack_bf2(float a, float b) {
    __nv_bfloat162 t = __floats2bfloat162_rn(a, b);
    return *(uint32_t*)&t;
}

__global__ void aprep_kernel(const float* __restrict__ in, int lda, int K,
                             __nv_bfloat16* __restrict__ out) {
    int half = K >> 1;
    int idx = blockIdx.x * 256 + threadIdx.x;
    if (idx >= NN * half) return;
    int m  = idx / half;
    int kk = (idx - m * half) * 2;
    float2 v = *(const float2*)&in[(size_t)m * lda + kk];
    float hx = __bfloat162float(__float2bfloat16(v.x));
    float hy = __bfloat162float(__float2bfloat16(v.y));
    uint32_t hi = pack_bf2(hx, hy);
    uint32_t lo = pack_bf2(v.x - hx, v.y - hy);
    size_t base = (size_t)m * (3 * K) + kk;
    *(uint32_t*)&out[base]         = hi;
    *(uint32_t*)&out[base + K]     = lo;
    *(uint32_t*)&out[base + 2 * K] = hi;
}

__device__ __forceinline__ void bprep_one(const float* __restrict__ W, int K,
                                          __nv_bfloat16* __restrict__ out, int idx) {
    int half = K >> 1;
    int n  = idx / half;
    int kk = (idx - n * half) * 2;
    float v0 = W[(size_t)kk * HD + n];
    float v1 = W[(size_t)(kk + 1) * HD + n];
    float h0 = __bfloat162float(__float2bfloat16(v0));
    float h1 = __bfloat162float(__float2bfloat16(v1));
    uint32_t hi = pack_bf2(h0, h1);
    uint32_t lo = pack_bf2(v0 - h0, v1 - h1);
    size_t base = (size_t)n * (3 * K) + kk;
    *(uint32_t*)&out[base]         = hi;
    *(uint32_t*)&out[base + K]     = hi;
    *(uint32_t*)&out[base + 2 * K] = lo;
}

__global__ void bprep_all_kernel(const float* __restrict__ W0, const float* __restrict__ W1,
                                 const float* __restrict__ W2, const float* __restrict__ W3,
                                 __nv_bfloat16* b0, __nv_bfloat16* b1,
                                 __nv_bfloat16* b2, __nv_bfloat16* b3) {
    const int t0 = HD * (FF0 / 2);
    const int t1 = HD * (HD / 2);
    int idx = blockIdx.x * 256 + threadIdx.x;
    if (idx < t0) { bprep_one(W0, FF0, b0, idx); return; }
    idx -= t0;
    if (idx < t1) { bprep_one(W1, HD, b1, idx); return; }
    idx -= t1;
    if (idx < t1) { bprep_one(W2, HD, b2, idx); return; }
    idx -= t1;
    if (idx < t1) { bprep_one(W3, HD, b3, idx); }
}

// ---------------- bf16 mma GEMM + fused es/ed epilogue --------------------------
// 256 thr, tile 128x128, 4-stage cp.async. Each warp's 64-col span == one head.
#define BK    32
#define LDP   40
#define STAGES 4
#define STAGE_ELEMS (128 * LDP)
#define GEMM_SMEM (STAGES * STAGE_ELEMS * 2 * 2)   // 81920 B

__device__ __forceinline__ uint32_t s2u(const void* p) {
    return (uint32_t)__cvta_generic_to_shared(p);
}

__global__ __launch_bounds__(256, 2)
void gemm_bf16(const __nv_bfloat16* __restrict__ A,   // [M][K3]
               const __nv_bfloat16* __restrict__ Bm,  // [512][K3]
               float* __restrict__ C, int M, int K3,
               const float* __restrict__ a_src,       // [8][64]
               const float* __restrict__ a_dst,
               float* __restrict__ es, float* __restrict__ ed) {
    extern __shared__ __nv_bfloat16 smem[];
    __nv_bfloat16* As = smem;
    __nv_bfloat16* Bs = smem + STAGES * STAGE_ELEMS;

    const int tid  = threadIdx.x;
    const int lane = tid & 31;
    const int wid  = tid >> 5;
    const int wm   = (wid & 3) * 32;
    const int wn   = (wid >> 2) * 64;
    const int bx   = blockIdx.x;
    const int by   = blockIdx.y;

    const int nchunks = K3 / BK;
    const int r0l = tid >> 2;
    const int seg = (tid & 3) * 8;

    float acc[2][8][4];
#pragma unroll
    for (int mt = 0; mt < 2; mt++)
#pragma unroll
        for (int nt = 0; nt < 8; nt++)
#pragma unroll
            for (int q = 0; q < 4; q++) acc[mt][nt][q] = 0.f;

    auto load_stage = [&](int c, int buf) {
        const __nv_bfloat16* Ac = A + c * BK;
        const __nv_bfloat16* Bc = Bm + c * BK;
        __nv_bfloat16* Asb = As + buf * STAGE_ELEMS;
        __nv_bfloat16* Bsb = Bs + buf * STAGE_ELEMS;
#pragma unroll
        for (int i = 0; i < 2; i++) {
            int r  = r0l + i * 64;
            int gr = by * 128 + r;
            int grc = gr < M ? gr : M - 1;
            uint32_t sa = s2u(&Asb[r * LDP + seg]);
            const void* ga = Ac + (size_t)grc * K3 + seg;
            int sz = (gr < M) ? 16 : 0;
            asm volatile("cp.async.cg.shared.global [%0], [%1], 16, %2;"
                         :: "r"(sa), "l"(ga), "r"(sz));
        }
#pragma unroll
        for (int i = 0; i < 2; i++) {
            int r  = r0l + i * 64;
            int gn = bx * 128 + r;
            uint32_t sb = s2u(&Bsb[r * LDP + seg]);
            const void* gb = Bc + (size_t)gn * K3 + seg;
            asm volatile("cp.async.cg.shared.global [%0], [%1], 16;"
                         :: "r"(sb), "l"(gb));
        }
        asm volatile("cp.async.commit_group;");
    };

    int pre = nchunks < (STAGES - 1) ? nchunks : (STAGES - 1);
    for (int s = 0; s < pre; s++) load_stage(s, s);

    for (int c = 0; c < nchunks; c++) {
        asm volatile("cp.async.wait_group %0;" :: "n"(STAGES - 2));
        __syncthreads();
        if (c + STAGES - 1 < nchunks) load_stage(c + STAGES - 1, (c + STAGES - 1) & (STAGES - 1));

        int buf = c & (STAGES - 1);
        const __nv_bfloat16* Asb = As + buf * STAGE_ELEMS;
        const __nv_bfloat16* Bsb = Bs + buf * STAGE_ELEMS;

#pragma unroll
        for (int kk = 0; kk < BK; kk += 16) {
            uint32_t a[2][4];
#pragma unroll
            for (int mt = 0; mt < 2; mt++) {
                int row = wm + mt * 16 + (lane & 15);
                uint32_t addr = s2u(&Asb[row * LDP + kk + ((lane >> 4) << 3)]);
                asm volatile("ldmatrix.sync.aligned.m8n8.x4.shared.b16 {%0,%1,%2,%3}, [%4];"
                             : "=r"(a[mt][0]), "=r"(a[mt][1]), "=r"(a[mt][2]), "=r"(a[mt][3])
                             : "r"(addr));
            }
            uint32_t b[8][2];
#pragma unroll
            for (int p = 0; p < 4; p++) {
                int row = wn + p * 16 + ((lane >> 4) << 3) + (lane & 7);
                uint32_t addr = s2u(&Bsb[row * LDP + kk + (((lane >> 3) & 1) << 3)]);
                uint32_t r0, r1, r2, r3;
                asm volatile("ldmatrix.sync.aligned.m8n8.x4.shared.b16 {%0,%1,%2,%3}, [%4];"
                             : "=r"(r0), "=r"(r1), "=r"(r2), "=r"(r3) : "r"(addr));
                b[2 * p][0] = r0; b[2 * p][1] = r1;
                b[2 * p + 1][0] = r2; b[2 * p + 1][1] = r3;
            }
#pragma unroll
            for (int nt = 0; nt < 8; nt++)
#pragma unroll
                for (int mt = 0; mt < 2; mt++) {
                    asm volatile(
                        "mma.sync.aligned.m16n8k16.row.col.f32.bf16.bf16.f32 "
                        "{%0,%1,%2,%3}, {%4,%5,%6,%7}, {%8,%9}, {%0,%1,%2,%3};"
                        : "+f"(acc[mt][nt][0]), "+f"(acc[mt][nt][1]),
                          "+f"(acc[mt][nt][2]), "+f"(acc[mt][nt][3])
                        : "r"(a[mt][0]), "r"(a[mt][1]), "r"(a[mt][2]), "r"(a[mt][3]),
                          "r"(b[nt][0]), "r"(b[nt][1]));
                }
        }
    }

    // ---- epilogue: store C and fused es/ed scores ----
    const int hwarp = bx * 2 + (wid >> 2);          // head for this warp's 64 cols
    const float* asr = a_src + hwarp * DD;
    const float* adr = a_dst + hwarp * DD;
    float esp[2][2] = {{0.f, 0.f}, {0.f, 0.f}};
    float edp[2][2] = {{0.f, 0.f}, {0.f, 0.f}};

#pragma unroll
    for (int mt = 0; mt < 2; mt++) {
        int row0 = by * 128 + wm + mt * 16 + (lane >> 2);
#pragma unroll
        for (int nt = 0; nt < 8; nt++) {
            int off = nt * 8 + (lane & 3) * 2;      // 0..63 within head
            float s0 = asr[off], s1 = asr[off + 1];
            float d0 = adr[off], d1 = adr[off + 1];
            esp[mt][0] += acc[mt][nt][0] * s0 + acc[mt][nt][1] * s1;
            esp[mt][1] += acc[mt][nt][2] * s0 + acc[mt][nt][3] * s1;
            edp[mt][0] += acc[mt][nt][0] * d0 + acc[mt][nt][1] * d1;
            edp[mt][1] += acc[mt][nt][2] * d0 + acc[mt][nt][3] * d1;

            int col = bx * 128 + wn + nt * 8 + (lane & 3) * 2;
            if (row0 < M)
                *(float2*)&C[(size_t)row0 * HD + col] =
                    make_float2(acc[mt][nt][0], acc[mt][nt][1]);
            if (row0 + 8 < M)
                *(float2*)&C[(size_t)(row0 + 8) * HD + col] =
                    make_float2(acc[mt][nt][2], acc[mt][nt][3]);
        }
        // quad reduction (lanes lane&3 within each group of 4)
#pragma unroll
        for (int r = 0; r < 2; r++) {
            esp[mt][r] += __shfl_down_sync(0xffffffffu, esp[mt][r], 1, 4);
            esp[mt][r] += __shfl_down_sync(0xffffffffu, esp[mt][r], 2, 4);
            edp[mt][r] += __shfl_down_sync(0xffffffffu, edp[mt][r], 1, 4);
            edp[mt][r] += __shfl_down_sync(0xffffffffu, edp[mt][r], 2, 4);
        }
        if ((lane & 3) == 0) {
            if (row0 < M) {
                es[(size_t)row0 * HH + hwarp] = esp[mt][0];
                ed[(size_t)row0 * HH + hwarp] = edp[mt][0];
            }
            if (row0 + 8 < M) {
                es[(size_t)(row0 + 8) * HH + hwarp] = esp[mt][1];
                ed[(size_t)(row0 + 8) * HH + hwarp] = edp[mt][1];
            }
        }
    }
}

// ---------------- fused GAT aggregation (+ optional bf16x3 emit, + cur reset) ----
__global__ __launch_bounds__(128)
void gat_agg_kernel(const float* __restrict__ hmat,
                    const int* __restrict__ csr,
                    const int* __restrict__ rowptr,
                    const float* __restrict__ es,
                    const float* __restrict__ ed,
                    const float* __restrict__ bias,
                    float* __restrict__ out, int ostride,
                    __nv_bfloat16* __restrict__ asplit,
                    int* __restrict__ cur_reset) {
    int n = blockIdx.x;
    int t = threadIdx.x;
    int beg = rowptr[n], end = rowptr[n + 1];
    int deg = end - beg;

    __shared__ float edn[8];
    __shared__ float red[16][8];
    __shared__ float mden[16];
    __shared__ int   ssh[ECAP];
    __shared__ float esh[ECAP][8];

    if (cur_reset && t == 0) cur_reset[n] = 0;
    if (t < 8) edn[t] = ed[(size_t)n * HH + t];
    for (int j = t; j < deg && j < ECAP; j += 128) ssh[j] = csr[beg + j];
    __syncthreads();

    int hh  = t & 7;
    int l16 = t >> 3;

    float mx = -INFINITY;
    for (int j = l16; j < deg; j += 16) {
        int s = (j < ECAP) ? ssh[j] : csr[beg + j];
        float e = es[(size_t)s * HH + hh] + edn[hh];
        e = e > 0.f ? e : 0.01f * e;
        if (j < ECAP) esh[j][hh] = e;
        mx = fmaxf(mx, e);
    }
    red[l16][hh] = mx;
    __syncthreads();
    if (t < 8) {
        float v = -INFINITY;
#pragma unroll
        for (int i = 0; i < 16; i++) v = fmaxf(v, red[i][t]);
        mden[t] = v;
    }
    __syncthreads();
    float m_h = mden[hh];

    float sm = 0.f;
    for (int j = l16; j < deg; j += 16) {
        float e;
        if (j < ECAP) e = esh[j][hh];
        else {
            int s = csr[beg + j];
            e = es[(size_t)s * HH + hh] + edn[hh];
            e = e > 0.f ? e : 0.01f * e;
        }
        float ex = __expf(e - m_h);
        if (j < ECAP) esh[j][hh] = ex;
        sm += ex;
    }
    red[l16][hh] = sm;
    __syncthreads();
    if (t < 8) {
        float v = 0.f;
#pragma unroll
        for (int i = 0; i < 16; i++) v += red[i][t];
        mden[8 + t] = 1.f / v;
    }
    __syncthreads();

    int hd = t >> 4;
    float invd = mden[8 + hd];
    float mh2  = mden[hd];
    int col = t * 4;
    float a0 = 0.f, a1 = 0.f, a2 = 0.f, a3 = 0.f;
#pragma unroll 4
    for (int j = 0; j < deg; j++) {
        int s; float ex;
        if (j < ECAP) { s = ssh[j]; ex = esh[j][hd]; }
        else {
            s = csr[beg + j];
            float e = es[(size_t)s * HH + hd] + edn[hd];
            e = e > 0.f ? e : 0.01f * e;
            ex = __expf(e - mh2);
        }
        float att = ex * invd;
        float4 hv = *(const float4*)&hmat[(size_t)s * HD + col];
        a0 += hv.x * att; a1 += hv.y * att; a2 += hv.z * att; a3 += hv.w * att;
    }
    float v0 = a0 + bias[col + 0];
    float v1 = a1 + bias[col + 1];
    float v2 = a2 + bias[col + 2];
    float v3 = a3 + bias[col + 3];
    float4 o;
    o.x = v0 > 0.f ? v0 : expm1f(v0);
    o.y = v1 > 0.f ? v1 : expm1f(v1);
    o.z = v2 > 0.f ? v2 : expm1f(v2);
    o.w = v3 > 0.f ? v3 : expm1f(v3);
    *(float4*)&out[(size_t)n * ostride + col] = o;

    if (asplit) {
        float h0 = __bfloat162float(__float2bfloat16(o.x));
        float h1 = __bfloat162float(__float2bfloat16(o.y));
        float h2 = __bfloat162float(__float2bfloat16(o.z));
        float h3 = __bfloat162float(__float2bfloat16(o.w));
        uint32_t hi01 = pack_bf2(h0, h1), hi23 = pack_bf2(h2, h3);
        uint32_t lo01 = pack_bf2(o.x - h0, o.y - h1);
        uint32_t lo23 = pack_bf2(o.z - h2, o.w - h3);
        size_t base = (size_t)n * 1536 + col;
        *(uint32_t*)&asplit[base]            = hi01;
        *(uint32_t*)&asplit[base + 2]        = hi23;
        *(uint32_t*)&asplit[base + 512]      = lo01;
        *(uint32_t*)&asplit[base + 514]      = lo23;
        *(uint32_t*)&asplit[base + 1024]     = hi01;
        *(uint32_t*)&asplit[base + 1026]     = hi23;
    }
}

// ---------------- residual ----------------
__global__ void resid_kernel(const float* __restrict__ x0, float* __restrict__ xc,
                             __nv_bfloat16* __restrict__ asplit) {
    int i = blockIdx.x * blockDim.x + threadIdx.x;
    if (i >= NN * HD) return;
    int n = i >> 9, j = i & 511;
    float v = x0[i] + xc[(size_t)n * XCW + 1024 + j];
    xc[(size_t)n * XCW + 1536 + j] = v;
    __nv_bfloat16 hb = __float2bfloat16(v);
    float hf = __bfloat162float(hb);
    size_t base = (size_t)n * 1536 + j;
    asplit[base]        = hb;
    asplit[base + 512]  = __float2bfloat16(v - hf);
    asplit[base + 1024] = hb;
}

// ---------------- pooling (binary search on sorted batch) ----------------
__global__ void pool_kernel(const float* __restrict__ xc, const int* __restrict__ batch,
                            float* __restrict__ pooled) {
    __shared__ int sb[2];
    int g = blockIdx.y;
    if (threadIdx.x < 2) {
        int target = g + threadIdx.x;
        int lo = 0, hi = NN;
        while (lo < hi) {
            int mid = (lo + hi) >> 1;
            if (batch[mid] < target) lo = mid + 1; else hi = mid;
        }
        sb[threadIdx.x] = lo;
    }
    __syncthreads();
    int beg = sb[0], end = sb[1];
    int col = blockIdx.x * 128 + threadIdx.x;
    float v = -INFINITY;
    for (int n = beg; n < end; n++)
        v = fmaxf(v, xc[(size_t)n * XCW + col]);
    if (!isfinite(v)) v = 0.f;
    pooled[g * XCW + col] = v;
}

// ---------------- MLP layer 1 ----------------
__global__ __launch_bounds__(128)
void mlp1_kernel(const float* __restrict__ pooled, const float* __restrict__ mW1,
                 const float* __restrict__ mb1, float* __restrict__ z) {
    __shared__ float ps[4][XCW];
    int j  = blockIdx.x * 128 + threadIdx.x;
    int g0 = blockIdx.y * 4;
#pragma unroll
    for (int gg = 0; gg < 4; gg++)
        for (int k = threadIdx.x; k < XCW; k += 128)
            ps[gg][k] = pooled[(g0 + gg) * XCW + k];
    __syncthreads();
    float acc[4];
#pragma unroll
    for (int gg = 0; gg < 4; gg++) acc[gg] = 0.f;
#pragma unroll 4
    for (int k = 0; k < XCW; k++) {
        float w = mW1[(size_t)k * HD + j];
#pragma unroll
        for (int gg = 0; gg < 4; gg++)
            acc[gg] += ps[gg][k] * w;
    }
    float bb = mb1[j];
#pragma unroll
    for (int gg = 0; gg < 4; gg++)
        z[(g0 + gg) * HD + j] = acc[gg] + bb;
}

// ---------------- BatchNorm + ReLU ----------------
__global__ void bn_relu_kernel(float* __restrict__ z, const float* __restrict__ gamma,
                               const float* __restrict__ beta) {
    int j = blockIdx.x;
    int t = threadIdx.x;
    __shared__ float part[2];
    float v = z[t * HD + j];
    float s = v;
#pragma unroll
    for (int o = 16; o; o >>= 1) s += __shfl_down_sync(0xffffffffu, s, o);
    if ((t & 31) == 0) part[t >> 5] = s;
    __syncthreads();
    float mu = (part[0] + part[1]) * (1.f / 64.f);
    __syncthreads();
    float dv = v - mu;
    float s2 = dv * dv;
#pragma unroll
    for (int o = 16; o; o >>= 1) s2 += __shfl_down_sync(0xffffffffu, s2, o);
    if ((t & 31) == 0) part[t >> 5] = s2;
    __syncthreads();
    float var = (part[0] + part[1]) * (1.f / 64.f);
    float norm = dv * rsqrtf(var + 1e-5f) * gamma[j] + beta[j];
    z[t * HD + j] = fmaxf(norm, 0.f);
}

// ---------------- final GEMM ----------------
__global__ void mlp2_kernel(const float* __restrict__ z, const float* __restrict__ mW2,
                            const float* __restrict__ mb2, float* __restrict__ out) {
    int t = threadIdx.x;
    if (t >= GG * CC) return;
    int g = t / CC, c = t % CC;
    float s = mb2[c];
    for (int k = 0; k < HD; k++) s += z[g * HD + k] * mW2[k * CC + c];
    out[t] = s;
}

// ---------------- host helpers ----------------
static void run_gemm(const __nv_bfloat16* pAB, const __nv_bfloat16* pBB,
                     float* pH, int K3,
                     const float* a_s, const float* a_d, float* pES, float* pED) {
    dim3 grid(HD / 128, (NN + 127) / 128);
    gemm_bf16<<<grid, 256, GEMM_SMEM>>>(pAB, pBB, pH, NN, K3, a_s, a_d, pES, pED);
}

extern "C" void kernel_launch(void* const* d_in, const int* in_sizes, int n_in,
                              void* d_out, int out_size) {
    (void)in_sizes; (void)n_in; (void)out_size;
    const float* x     = (const float*)d_in[0];
    const int*   ei    = (const int*)  d_in[1];
    const int*   batch = (const int*)  d_in[2];
    const float* W0  = (const float*)d_in[3];
    const float* as0 = (const float*)d_in[4];
    const float* ad0 = (const float*)d_in[5];
    const float* b0  = (const float*)d_in[6];
    const float* W1  = (const float*)d_in[7];
    const float* as1 = (const float*)d_in[8];
    const float* ad1 = (const float*)d_in[9];
    const float* b1  = (const float*)d_in[10];
    const float* W2  = (const float*)d_in[11];
    const float* as2 = (const float*)d_in[12];
    const float* ad2 = (const float*)d_in[13];
    const float* b2  = (const float*)d_in[14];
    const float* W3  = (const float*)d_in[15];
    const float* as3 = (const float*)d_in[16];
    const float* ad3 = (const float*)d_in[17];
    const float* b3  = (const float*)d_in[18];
    const float* mW1 = (const float*)d_in[19];
    const float* mb1 = (const float*)d_in[20];
    const float* gam = (const float*)d_in[21];
    const float* bet = (const float*)d_in[22];
    const float* mW2 = (const float*)d_in[23];
    const float* mb2 = (const float*)d_in[24];
    float* outp = (float*)d_out;

    const int* src = ei;
    const int* dst = ei + EE;

    float *pH, *pX0, *pXC, *pES, *pED, *pPOOL, *pZ;
    int *pCNT, *pCUR, *pROW, *pCSR;
    __nv_bfloat16 *pAB, *pBB0, *pBB1, *pBB2, *pBB3;
    cudaGetSymbolAddress((void**)&pH,   g_h);
    cudaGetSymbolAddress((void**)&pX0,  g_x0);
    cudaGetSymbolAddress((void**)&pXC,  g_xc);
    cudaGetSymbolAddress((void**)&pES,  g_es);
    cudaGetSymbolAddress((void**)&pED,  g_ed);
    cudaGetSymbolAddress((void**)&pPOOL,g_pool);
    cudaGetSymbolAddress((void**)&pZ,   g_z);
    cudaGetSymbolAddress((void**)&pCNT, g_cnt);
    cudaGetSymbolAddress((void**)&pCUR, g_cur);
    cudaGetSymbolAddress((void**)&pROW, g_rowptr);
    cudaGetSymbolAddress((void**)&pCSR, g_csr);
    cudaGetSymbolAddress((void**)&pAB,  g_ab);
    cudaGetSymbolAddress((void**)&pBB0, g_bb0);
    cudaGetSymbolAddress((void**)&pBB1, g_bb1);
    cudaGetSymbolAddress((void**)&pBB2, g_bb2);
    cudaGetSymbolAddress((void**)&pBB3, g_bb3);

    cudaFuncSetAttribute(gemm_bf16, cudaFuncAttributeMaxDynamicSharedMemorySize, GEMM_SMEM);

    const int bprep_total = HD * (FF0 / 2) + 3 * HD * (HD / 2);

    // cnt/cur zero on entry (static init / recycled by scan + gat_agg layer0)
    aprep_kernel<<<(NN * (FF0 / 2) + 255) / 256, 256>>>(x, FF0, FF0, pAB);   // 1
    bprep_all_kernel<<<(bprep_total + 255) / 256, 256>>>(W0, W1, W2, W3,
                                                         pBB0, pBB1, pBB2, pBB3); // 2
    hist_kernel<<<(EE + 255) / 256, 256>>>(dst, pCNT);                       // 3
    run_gemm(pAB, pBB0, pH, 3 * FF0, as0, ad0, pES, pED);                    // 4 <-- profiled
    scan_kernel<<<1, 1024>>>(pCNT, pROW);                                    // 5
    scatter_kernel<<<(EE + 255) / 256, 256>>>(src, dst, pROW, pCUR, pCSR);   // 6
    gat_agg_kernel<<<NN, 128>>>(pH, pCSR, pROW, pES, pED, b0, pX0, HD, pAB, pCUR); // 7

    // Layer 1 (head)
    run_gemm(pAB, pBB1, pH, 3 * HD, as1, ad1, pES, pED);
    gat_agg_kernel<<<NN, 128>>>(pH, pCSR, pROW, pES, pED, b1, pXC + 512, XCW, pAB, nullptr);

    // Layer 2 (body)
    run_gemm(pAB, pBB2, pH, 3 * HD, as2, ad2, pES, pED);
    gat_agg_kernel<<<NN, 128>>>(pH, pCSR, pROW, pES, pED, b2, pXC + 1024, XCW, nullptr, nullptr);

    // Residual -> x3 (emits split), Layer 3 (tail)
    resid_kernel<<<(NN * HD + 255) / 256, 256>>>(pX0, pXC, pAB);
    run_gemm(pAB, pBB3, pH, 3 * HD, as3, ad3, pES, pED);
    gat_agg_kernel<<<NN, 128>>>(pH, pCSR, pROW, pES, pED, b3, pXC, XCW, nullptr, nullptr);

    // Pool + MLP head
    pool_kernel<<<dim3(XCW / 128, GG), 128>>>(pXC, batch, pPOOL);
    mlp1_kernel<<<dim3(HD / 128, GG / 4), 128>>>(pPOOL, mW1, mb1, pZ);
    bn_relu_kernel<<<HD, 64>>>(pZ, gam, bet);
    mlp2_kernel<<<1, GG * CC>>>(pZ, mW2, mb2, outp);
}

// round 15
// speedup vs baseline: 1.2078x; 1.0217x over previous
#include <cuda_runtime.h>
#include <cuda_bf16.h>
#include <math.h>
#include <stdint.h>

// Problem constants
#define NN   10000
#define EE   150000
#define FF0  128
#define HH   8
#define DD   64
#define HD   512
#define GG   64
#define CC   10
#define XCW  2048
#define ECAP 96

// ---------------- device scratch ----------------
__device__ float g_h [(size_t)NN*HD];
__device__ float g_x0[(size_t)NN*HD];
__device__ float g_xc[(size_t)NN*XCW];
__device__ float g_es[(size_t)NN*HH];
__device__ float g_ed[(size_t)NN*HH];
__device__ float g_pool[GG*XCW];
__device__ float g_z  [GG*HD];
__device__ int   g_cnt[NN];      // zero-initialized; scan re-zeroes each run
__device__ int   g_cur[NN];      // zero-initialized; gat_agg layer0 re-zeroes
__device__ int   g_rowptr[NN+1];
__device__ int   g_csr[EE];
// bf16x3-split operands
__device__ __nv_bfloat16 g_ab [(size_t)NN*1536];
__device__ __nv_bfloat16 g_bb0[(size_t)HD*384];
__device__ __nv_bfloat16 g_bb1[(size_t)HD*1536];
__device__ __nv_bfloat16 g_bb2[(size_t)HD*1536];
__device__ __nv_bfloat16 g_bb3[(size_t)HD*1536];

// ---------------- utility kernels ----------------
__global__ void hist_kernel(const int* __restrict__ dst, int* __restrict__ cnt) {
    int i = blockIdx.x * blockDim.x + threadIdx.x;
    if (i < EE) atomicAdd(&cnt[dst[i]], 1);
}

// single block, 1024 threads; exclusive scan of cnt into rowptr; zeroes cnt after read
__global__ void scan_kernel(int* __restrict__ cnt, int* __restrict__ rowptr) {
    __shared__ int sums[1024];
    int t = threadIdx.x;
    int base = t * 10;
    int loc[10];
    int s = 0;
#pragma unroll
    for (int i = 0; i < 10; i++) {
        loc[i] = s;
        int idx = base + i;
        if (idx < NN) { s += cnt[idx]; cnt[idx] = 0; }
    }
    int tot = s;
    sums[t] = s;
    __syncthreads();
    for (int off = 1; off < 1024; off <<= 1) {
        int v = (t >= off) ? sums[t - off] : 0;
        __syncthreads();
        sums[t] += v;
        __syncthreads();
    }
    int excl = sums[t] - tot;
#pragma unroll
    for (int i = 0; i < 10; i++) {
        int idx = base + i;
        if (idx < NN) rowptr[idx] = excl + loc[i];
    }
    if (t == 1023) rowptr[NN] = sums[1023];
}

__global__ void scatter_kernel(const int* __restrict__ src, const int* __restrict__ dst,
                               const int* __restrict__ rowptr, int* __restrict__ cur,
                               int* __restrict__ csr) {
    int i = blockIdx.x * blockDim.x + threadIdx.x;
    if (i >= EE) return;
    int d = dst[i];
    int pos = atomicAdd(&cur[d], 1);
    csr[rowptr[d] + pos] = src[i];
}

// ---------------- bf16x3 split prep ----------------
__device__ __forceinline__ uint32_t pack_bf2(float a, float b) {
    __nv_bfloat162 t = __floats2bfloat162_rn(a, b);
    return *(uint32_t*)&t;
}

__global__ void aprep_kernel(const float* __restrict__ in, int lda, int K,
                             __nv_bfloat16* __restrict__ out) {
    int half = K >> 1;
    int idx = blockIdx.x * 256 + threadIdx.x;
    if (idx >= NN * half) return;
    int m  = idx / half;
    int kk = (idx - m * half) * 2;
    float2 v = *(const float2*)&in[(size_t)m * lda + kk];
    float hx = __bfloat162float(__float2bfloat16(v.x));
    float hy = __bfloat162float(__float2bfloat16(v.y));
    uint32_t hi = pack_bf2(hx, hy);
    uint32_t lo = pack_bf2(v.x - hx, v.y - hy);
    size_t base = (size_t)m * (3 * K) + kk;
    *(uint32_t*)&out[base]         = hi;
    *(uint32_t*)&out[base + K]     = lo;
    *(uint32_t*)&out[base + 2 * K] = hi;
}

__device__ __forceinline__ void bprep_one(const float* __restrict__ W, int K,
                                          __nv_bfloat16* __restrict__ out, int idx) {
    int half = K >> 1;
    int n  = idx / half;
    int kk = (idx - n * half) * 2;
    float v0 = W[(size_t)kk * HD + n];
    float v1 = W[(size_t)(kk + 1) * HD + n];
    float h0 = __bfloat162float(__float2bfloat16(v0));
    float h1 = __bfloat162float(__float2bfloat16(v1));
    uint32_t hi = pack_bf2(h0, h1);
    uint32_t lo = pack_bf2(v0 - h0, v1 - h1);
    size_t base = (size_t)n * (3 * K) + kk;
    *(uint32_t*)&out[base]         = hi;
    *(uint32_t*)&out[base + K]     = hi;
    *(uint32_t*)&out[base + 2 * K] = lo;
}

__global__ void bprep_all_kernel(const float* __restrict__ W0, const float* __restrict__ W1,
                                 const float* __restrict__ W2, const float* __restrict__ W3,
                                 __nv_bfloat16* b0, __nv_bfloat16* b1,
                                 __nv_bfloat16* b2, __nv_bfloat16* b3) {
    const int t0 = HD * (FF0 / 2);
    const int t1 = HD * (HD / 2);
    int idx = blockIdx.x * 256 + threadIdx.x;
    if (idx < t0) { bprep_one(W0, FF0, b0, idx); return; }
    idx -= t0;
    if (idx < t1) { bprep_one(W1, HD, b1, idx); return; }
    idx -= t1;
    if (idx < t1) { bprep_one(W2, HD, b2, idx); return; }
    idx -= t1;
    if (idx < t1) { bprep_one(W3, HD, b3, idx); }
}

// ---------------- bf16 mma GEMM + fused es/ed epilogue --------------------------
#define BK    32
#define LDP   40
#define STAGES 4
#define STAGE_ELEMS (128 * LDP)
#define GEMM_SMEM (STAGES * STAGE_ELEMS * 2 * 2)   // 81920 B

__device__ __forceinline__ uint32_t s2u(const void* p) {
    return (uint32_t)__cvta_generic_to_shared(p);
}

__global__ __launch_bounds__(256, 2)
void gemm_bf16(const __nv_bfloat16* __restrict__ A,   // [M][K3]
               const __nv_bfloat16* __restrict__ Bm,  // [512][K3]
               float* __restrict__ C, int M, int K3,
               const float* __restrict__ a_src,       // [8][64]
               const float* __restrict__ a_dst,
               float* __restrict__ es, float* __restrict__ ed) {
    extern __shared__ __nv_bfloat16 smem[];
    __nv_bfloat16* As = smem;
    __nv_bfloat16* Bs = smem + STAGES * STAGE_ELEMS;

    const int tid  = threadIdx.x;
    const int lane = tid & 31;
    const int wid  = tid >> 5;
    const int wm   = (wid & 3) * 32;
    const int wn   = (wid >> 2) * 64;
    const int bx   = blockIdx.x;
    const int by   = blockIdx.y;

    const int nchunks = K3 / BK;
    const int r0l = tid >> 2;
    const int seg = (tid & 3) * 8;

    float acc[2][8][4];
#pragma unroll
    for (int mt = 0; mt < 2; mt++)
#pragma unroll
        for (int nt = 0; nt < 8; nt++)
#pragma unroll
            for (int q = 0; q < 4; q++) acc[mt][nt][q] = 0.f;

    auto load_stage = [&](int c, int buf) {
        const __nv_bfloat16* Ac = A + c * BK;
        const __nv_bfloat16* Bc = Bm + c * BK;
        __nv_bfloat16* Asb = As + buf * STAGE_ELEMS;
        __nv_bfloat16* Bsb = Bs + buf * STAGE_ELEMS;
#pragma unroll
        for (int i = 0; i < 2; i++) {
            int r  = r0l + i * 64;
            int gr = by * 128 + r;
            int grc = gr < M ? gr : M - 1;
            uint32_t sa = s2u(&Asb[r * LDP + seg]);
            const void* ga = Ac + (size_t)grc * K3 + seg;
            int sz = (gr < M) ? 16 : 0;
            asm volatile("cp.async.cg.shared.global [%0], [%1], 16, %2;"
                         :: "r"(sa), "l"(ga), "r"(sz));
        }
#pragma unroll
        for (int i = 0; i < 2; i++) {
            int r  = r0l + i * 64;
            int gn = bx * 128 + r;
            uint32_t sb = s2u(&Bsb[r * LDP + seg]);
            const void* gb = Bc + (size_t)gn * K3 + seg;
            asm volatile("cp.async.cg.shared.global [%0], [%1], 16;"
                         :: "r"(sb), "l"(gb));
        }
        asm volatile("cp.async.commit_group;");
    };

    int pre = nchunks < (STAGES - 1) ? nchunks : (STAGES - 1);
    for (int s = 0; s < pre; s++) load_stage(s, s);

    for (int c = 0; c < nchunks; c++) {
        asm volatile("cp.async.wait_group %0;" :: "n"(STAGES - 2));
        __syncthreads();
        if (c + STAGES - 1 < nchunks) load_stage(c + STAGES - 1, (c + STAGES - 1) & (STAGES - 1));

        int buf = c & (STAGES - 1);
        const __nv_bfloat16* Asb = As + buf * STAGE_ELEMS;
        const __nv_bfloat16* Bsb = Bs + buf * STAGE_ELEMS;

#pragma unroll
        for (int kk = 0; kk < BK; kk += 16) {
            uint32_t a[2][4];
#pragma unroll
            for (int mt = 0; mt < 2; mt++) {
                int row = wm + mt * 16 + (lane & 15);
                uint32_t addr = s2u(&Asb[row * LDP + kk + ((lane >> 4) << 3)]);
                asm volatile("ldmatrix.sync.aligned.m8n8.x4.shared.b16 {%0,%1,%2,%3}, [%4];"
                             : "=r"(a[mt][0]), "=r"(a[mt][1]), "=r"(a[mt][2]), "=r"(a[mt][3])
                             : "r"(addr));
            }
            uint32_t b[8][2];
#pragma unroll
            for (int p = 0; p < 4; p++) {
                int row = wn + p * 16 + ((lane >> 4) << 3) + (lane & 7);
                uint32_t addr = s2u(&Bsb[row * LDP + kk + (((lane >> 3) & 1) << 3)]);
                uint32_t r0, r1, r2, r3;
                asm volatile("ldmatrix.sync.aligned.m8n8.x4.shared.b16 {%0,%1,%2,%3}, [%4];"
                             : "=r"(r0), "=r"(r1), "=r"(r2), "=r"(r3) : "r"(addr));
                b[2 * p][0] = r0; b[2 * p][1] = r1;
                b[2 * p + 1][0] = r2; b[2 * p + 1][1] = r3;
            }
#pragma unroll
            for (int nt = 0; nt < 8; nt++)
#pragma unroll
                for (int mt = 0; mt < 2; mt++) {
                    asm volatile(
                        "mma.sync.aligned.m16n8k16.row.col.f32.bf16.bf16.f32 "
                        "{%0,%1,%2,%3}, {%4,%5,%6,%7}, {%8,%9}, {%0,%1,%2,%3};"
                        : "+f"(acc[mt][nt][0]), "+f"(acc[mt][nt][1]),
                          "+f"(acc[mt][nt][2]), "+f"(acc[mt][nt][3])
                        : "r"(a[mt][0]), "r"(a[mt][1]), "r"(a[mt][2]), "r"(a[mt][3]),
                          "r"(b[nt][0]), "r"(b[nt][1]));
                }
        }
    }

    // ---- epilogue: store C and fused es/ed scores ----
    const int hwarp = bx * 2 + (wid >> 2);
    const float* asr = a_src + hwarp * DD;
    const float* adr = a_dst + hwarp * DD;
    float esp[2][2] = {{0.f, 0.f}, {0.f, 0.f}};
    float edp[2][2] = {{0.f, 0.f}, {0.f, 0.f}};

#pragma unroll
    for (int mt = 0; mt < 2; mt++) {
        int row0 = by * 128 + wm + mt * 16 + (lane >> 2);
#pragma unroll
        for (int nt = 0; nt < 8; nt++) {
            int off = nt * 8 + (lane & 3) * 2;
            float s0 = asr[off], s1 = asr[off + 1];
            float d0 = adr[off], d1 = adr[off + 1];
            esp[mt][0] += acc[mt][nt][0] * s0 + acc[mt][nt][1] * s1;
            esp[mt][1] += acc[mt][nt][2] * s0 + acc[mt][nt][3] * s1;
            edp[mt][0] += acc[mt][nt][0] * d0 + acc[mt][nt][1] * d1;
            edp[mt][1] += acc[mt][nt][2] * d0 + acc[mt][nt][3] * d1;

            int col = bx * 128 + wn + nt * 8 + (lane & 3) * 2;
            if (row0 < M)
                *(float2*)&C[(size_t)row0 * HD + col] =
                    make_float2(acc[mt][nt][0], acc[mt][nt][1]);
            if (row0 + 8 < M)
                *(float2*)&C[(size_t)(row0 + 8) * HD + col] =
                    make_float2(acc[mt][nt][2], acc[mt][nt][3]);
        }
#pragma unroll
        for (int r = 0; r < 2; r++) {
            esp[mt][r] += __shfl_down_sync(0xffffffffu, esp[mt][r], 1, 4);
            esp[mt][r] += __shfl_down_sync(0xffffffffu, esp[mt][r], 2, 4);
            edp[mt][r] += __shfl_down_sync(0xffffffffu, edp[mt][r], 1, 4);
            edp[mt][r] += __shfl_down_sync(0xffffffffu, edp[mt][r], 2, 4);
        }
        if ((lane & 3) == 0) {
            if (row0 < M) {
                es[(size_t)row0 * HH + hwarp] = esp[mt][0];
                ed[(size_t)row0 * HH + hwarp] = edp[mt][0];
            }
            if (row0 + 8 < M) {
                es[(size_t)(row0 + 8) * HH + hwarp] = esp[mt][1];
                ed[(size_t)(row0 + 8) * HH + hwarp] = edp[mt][1];
            }
        }
    }
}

// ---------------- fused GAT aggregation ------------------------------------------
// Optional: bf16x3 emit (asplit), cur reset (layer0), residual fusion (x0add):
//   when x0add != null: out gets x2; out[.. + 512] gets x3 = x0 + x2;
//   asplit (if set) receives split of x3 instead of x2.
__global__ __launch_bounds__(128)
void gat_agg_kernel(const float* __restrict__ hmat,
                    const int* __restrict__ csr,
                    const int* __restrict__ rowptr,
                    const float* __restrict__ es,
                    const float* __restrict__ ed,
                    const float* __restrict__ bias,
                    float* __restrict__ out, int ostride,
                    __nv_bfloat16* __restrict__ asplit,
                    int* __restrict__ cur_reset,
                    const float* __restrict__ x0add) {
    int n = blockIdx.x;
    int t = threadIdx.x;
    int beg = rowptr[n], end = rowptr[n + 1];
    int deg = end - beg;

    __shared__ float edn[8];
    __shared__ float red[16][8];
    __shared__ float mden[16];
    __shared__ int   ssh[ECAP];
    __shared__ float esh[ECAP][8];

    if (cur_reset && t == 0) cur_reset[n] = 0;
    if (t < 8) edn[t] = ed[(size_t)n * HH + t];
    for (int j = t; j < deg && j < ECAP; j += 128) ssh[j] = csr[beg + j];
    __syncthreads();

    int hh  = t & 7;
    int l16 = t >> 3;

    float mx = -INFINITY;
    for (int j = l16; j < deg; j += 16) {
        int s = (j < ECAP) ? ssh[j] : csr[beg + j];
        float e = es[(size_t)s * HH + hh] + edn[hh];
        e = e > 0.f ? e : 0.01f * e;
        if (j < ECAP) esh[j][hh] = e;
        mx = fmaxf(mx, e);
    }
    red[l16][hh] = mx;
    __syncthreads();
    if (t < 8) {
        float v = -INFINITY;
#pragma unroll
        for (int i = 0; i < 16; i++) v = fmaxf(v, red[i][t]);
        mden[t] = v;
    }
    __syncthreads();
    float m_h = mden[hh];

    float sm = 0.f;
    for (int j = l16; j < deg; j += 16) {
        float e;
        if (j < ECAP) e = esh[j][hh];
        else {
            int s = csr[beg + j];
            e = es[(size_t)s * HH + hh] + edn[hh];
            e = e > 0.f ? e : 0.01f * e;
        }
        float ex = __expf(e - m_h);
        if (j < ECAP) esh[j][hh] = ex;
        sm += ex;
    }
    red[l16][hh] = sm;
    __syncthreads();
    if (t < 8) {
        float v = 0.f;
#pragma unroll
        for (int i = 0; i < 16; i++) v += red[i][t];
        mden[8 + t] = 1.f / v;
    }
    __syncthreads();

    int hd = t >> 4;
    float invd = mden[8 + hd];
    float mh2  = mden[hd];
    int col = t * 4;
    float a0 = 0.f, a1 = 0.f, a2 = 0.f, a3 = 0.f;
#pragma unroll 8
    for (int j = 0; j < deg; j++) {
        int s; float ex;
        if (j < ECAP) { s = ssh[j]; ex = esh[j][hd]; }
        else {
            s = csr[beg + j];
            float e = es[(size_t)s * HH + hd] + edn[hd];
            e = e > 0.f ? e : 0.01f * e;
            ex = __expf(e - mh2);
        }
        float att = ex * invd;
        float4 hv = *(const float4*)&hmat[(size_t)s * HD + col];
        a0 += hv.x * att; a1 += hv.y * att; a2 += hv.z * att; a3 += hv.w * att;
    }
    float v0 = a0 + bias[col + 0];
    float v1 = a1 + bias[col + 1];
    float v2 = a2 + bias[col + 2];
    float v3 = a3 + bias[col + 3];
    float4 o;
    o.x = v0 > 0.f ? v0 : expm1f(v0);
    o.y = v1 > 0.f ? v1 : expm1f(v1);
    o.z = v2 > 0.f ? v2 : expm1f(v2);
    o.w = v3 > 0.f ? v3 : expm1f(v3);
    *(float4*)&out[(size_t)n * ostride + col] = o;

    float4 w = o;   // value to split-emit (x2, or x3 when residual-fused)
    if (x0add) {
        float4 xv = *(const float4*)&x0add[(size_t)n * HD + col];
        w.x = o.x + xv.x; w.y = o.y + xv.y;
        w.z = o.z + xv.z; w.w = o.w + xv.w;
        *(float4*)&out[(size_t)n * ostride + 512 + col] = w;   // x3 slice
    }

    if (asplit) {
        float h0 = __bfloat162float(__float2bfloat16(w.x));
        float h1 = __bfloat162float(__float2bfloat16(w.y));
        float h2 = __bfloat162float(__float2bfloat16(w.z));
        float h3 = __bfloat162float(__float2bfloat16(w.w));
        uint32_t hi01 = pack_bf2(h0, h1), hi23 = pack_bf2(h2, h3);
        uint32_t lo01 = pack_bf2(w.x - h0, w.y - h1);
        uint32_t lo23 = pack_bf2(w.z - h2, w.w - h3);
        size_t base = (size_t)n * 1536 + col;
        *(uint32_t*)&asplit[base]            = hi01;
        *(uint32_t*)&asplit[base + 2]        = hi23;
        *(uint32_t*)&asplit[base + 512]      = lo01;
        *(uint32_t*)&asplit[base + 514]      = lo23;
        *(uint32_t*)&asplit[base + 1024]     = hi01;
        *(uint32_t*)&asplit[base + 1026]     = hi23;
    }
}

// ---------------- pooling (binary search on sorted batch) ----------------
__global__ void pool_kernel(const float* __restrict__ xc, const int* __restrict__ batch,
                            float* __restrict__ pooled) {
    __shared__ int sb[2];
    int g = blockIdx.y;
    if (threadIdx.x < 2) {
        int target = g + threadIdx.x;
        int lo = 0, hi = NN;
        while (lo < hi) {
            int mid = (lo + hi) >> 1;
            if (batch[mid] < target) lo = mid + 1; else hi = mid;
        }
        sb[threadIdx.x] = lo;
    }
    __syncthreads();
    int beg = sb[0], end = sb[1];
    int col = blockIdx.x * 128 + threadIdx.x;
    float v = -INFINITY;
    for (int n = beg; n < end; n++)
        v = fmaxf(v, xc[(size_t)n * XCW + col]);
    if (!isfinite(v)) v = 0.f;
    pooled[g * XCW + col] = v;
}

// ---------------- MLP layer 1 ----------------
__global__ __launch_bounds__(128)
void mlp1_kernel(const float* __restrict__ pooled, const float* __restrict__ mW1,
                 const float* __restrict__ mb1, float* __restrict__ z) {
    __shared__ float ps[4][XCW];
    int j  = blockIdx.x * 128 + threadIdx.x;
    int g0 = blockIdx.y * 4;
#pragma unroll
    for (int gg = 0; gg < 4; gg++)
        for (int k = threadIdx.x; k < XCW; k += 128)
            ps[gg][k] = pooled[(g0 + gg) * XCW + k];
    __syncthreads();
    float acc[4];
#pragma unroll
    for (int gg = 0; gg < 4; gg++) acc[gg] = 0.f;
#pragma unroll 4
    for (int k = 0; k < XCW; k++) {
        float w = mW1[(size_t)k * HD + j];
#pragma unroll
        for (int gg = 0; gg < 4; gg++)
            acc[gg] += ps[gg][k] * w;
    }
    float bb = mb1[j];
#pragma unroll
    for (int gg = 0; gg < 4; gg++)
        z[(g0 + gg) * HD + j] = acc[gg] + bb;
}

// ---------------- BatchNorm + ReLU ----------------
__global__ void bn_relu_kernel(float* __restrict__ z, const float* __restrict__ gamma,
                               const float* __restrict__ beta) {
    int j = blockIdx.x;
    int t = threadIdx.x;
    __shared__ float part[2];
    float v = z[t * HD + j];
    float s = v;
#pragma unroll
    for (int o = 16; o; o >>= 1) s += __shfl_down_sync(0xffffffffu, s, o);
    if ((t & 31) == 0) part[t >> 5] = s;
    __syncthreads();
    float mu = (part[0] + part[1]) * (1.f / 64.f);
    __syncthreads();
    float dv = v - mu;
    float s2 = dv * dv;
#pragma unroll
    for (int o = 16; o; o >>= 1) s2 += __shfl_down_sync(0xffffffffu, s2, o);
    if ((t & 31) == 0) part[t >> 5] = s2;
    __syncthreads();
    float var = (part[0] + part[1]) * (1.f / 64.f);
    float norm = dv * rsqrtf(var + 1e-5f) * gamma[j] + beta[j];
    z[t * HD + j] = fmaxf(norm, 0.f);
}

// ---------------- final GEMM ----------------
__global__ void mlp2_kernel(const float* __restrict__ z, const float* __restrict__ mW2,
                            const float* __restrict__ mb2, float* __restrict__ out) {
    int t = threadIdx.x;
    if (t >= GG * CC) return;
    int g = t / CC, c = t % CC;
    float s = mb2[c];
    for (int k = 0; k < HD; k++) s += z[g * HD + k] * mW2[k * CC + c];
    out[t] = s;
}

// ---------------- host helpers ----------------
static void run_gemm(const __nv_bfloat16* pAB, const __nv_bfloat16* pBB,
                     float* pH, int K3,
                     const float* a_s, const float* a_d, float* pES, float* pED) {
    dim3 grid(HD / 128, (NN + 127) / 128);
    gemm_bf16<<<grid, 256, GEMM_SMEM>>>(pAB, pBB, pH, NN, K3, a_s, a_d, pES, pED);
}

extern "C" void kernel_launch(void* const* d_in, const int* in_sizes, int n_in,
                              void* d_out, int out_size) {
    (void)in_sizes; (void)n_in; (void)out_size;
    const float* x     = (const float*)d_in[0];
    const int*   ei    = (const int*)  d_in[1];
    const int*   batch = (const int*)  d_in[2];
    const float* W0  = (const float*)d_in[3];
    const float* as0 = (const float*)d_in[4];
    const float* ad0 = (const float*)d_in[5];
    const float* b0  = (const float*)d_in[6];
    const float* W1  = (const float*)d_in[7];
    const float* as1 = (const float*)d_in[8];
    const float* ad1 = (const float*)d_in[9];
    const float* b1  = (const float*)d_in[10];
    const float* W2  = (const float*)d_in[11];
    const float* as2 = (const float*)d_in[12];
    const float* ad2 = (const float*)d_in[13];
    const float* b2  = (const float*)d_in[14];
    const float* W3  = (const float*)d_in[15];
    const float* as3 = (const float*)d_in[16];
    const float* ad3 = (const float*)d_in[17];
    const float* b3  = (const float*)d_in[18];
    const float* mW1 = (const float*)d_in[19];
    const float* mb1 = (const float*)d_in[20];
    const float* gam = (const float*)d_in[21];
    const float* bet = (const float*)d_in[22];
    const float* mW2 = (const float*)d_in[23];
    const float* mb2 = (const float*)d_in[24];
    float* outp = (float*)d_out;

    const int* src = ei;
    const int* dst = ei + EE;

    float *pH, *pX0, *pXC, *pES, *pED, *pPOOL, *pZ;
    int *pCNT, *pCUR, *pROW, *pCSR;
    __nv_bfloat16 *pAB, *pBB0, *pBB1, *pBB2, *pBB3;
    cudaGetSymbolAddress((void**)&pH,   g_h);
    cudaGetSymbolAddress((void**)&pX0,  g_x0);
    cudaGetSymbolAddress((void**)&pXC,  g_xc);
    cudaGetSymbolAddress((void**)&pES,  g_es);
    cudaGetSymbolAddress((void**)&pED,  g_ed);
    cudaGetSymbolAddress((void**)&pPOOL,g_pool);
    cudaGetSymbolAddress((void**)&pZ,   g_z);
    cudaGetSymbolAddress((void**)&pCNT, g_cnt);
    cudaGetSymbolAddress((void**)&pCUR, g_cur);
    cudaGetSymbolAddress((void**)&pROW, g_rowptr);
    cudaGetSymbolAddress((void**)&pCSR, g_csr);
    cudaGetSymbolAddress((void**)&pAB,  g_ab);
    cudaGetSymbolAddress((void**)&pBB0, g_bb0);
    cudaGetSymbolAddress((void**)&pBB1, g_bb1);
    cudaGetSymbolAddress((void**)&pBB2, g_bb2);
    cudaGetSymbolAddress((void**)&pBB3, g_bb3);

    cudaFuncSetAttribute(gemm_bf16, cudaFuncAttributeMaxDynamicSharedMemorySize, GEMM_SMEM);

    const int bprep_total = HD * (FF0 / 2) + 3 * HD * (HD / 2);

    // cnt/cur zero on entry (static init / recycled by scan + gat_agg layer0)
    aprep_kernel<<<(NN * (FF0 / 2) + 255) / 256, 256>>>(x, FF0, FF0, pAB);   // 1
    bprep_all_kernel<<<(bprep_total + 255) / 256, 256>>>(W0, W1, W2, W3,
                                                         pBB0, pBB1, pBB2, pBB3); // 2
    hist_kernel<<<(EE + 255) / 256, 256>>>(dst, pCNT);                       // 3
    run_gemm(pAB, pBB0, pH, 3 * FF0, as0, ad0, pES, pED);                    // 4 <-- profiled
    scan_kernel<<<1, 1024>>>(pCNT, pROW);                                    // 5
    scatter_kernel<<<(EE + 255) / 256, 256>>>(src, dst, pROW, pCUR, pCSR);   // 6
    gat_agg_kernel<<<NN, 128>>>(pH, pCSR, pROW, pES, pED, b0,
                                pX0, HD, pAB, pCUR, nullptr);                // 7

    // Layer 1 (head) -> xc[512:1024]
    run_gemm(pAB, pBB1, pH, 3 * HD, as1, ad1, pES, pED);
    gat_agg_kernel<<<NN, 128>>>(pH, pCSR, pROW, pES, pED, b1,
                                pXC + 512, XCW, pAB, nullptr, nullptr);

    // Layer 2 (body) -> xc[1024:1536]; fused residual x3 -> xc[1536:2048] + split
    run_gemm(pAB, pBB2, pH, 3 * HD, as2, ad2, pES, pED);
    gat_agg_kernel<<<NN, 128>>>(pH, pCSR, pROW, pES, pED, b2,
                                pXC + 1024, XCW, pAB, nullptr, pX0);

    // Layer 3 (tail) -> xc[0:512]
    run_gemm(pAB, pBB3, pH, 3 * HD, as3, ad3, pES, pED);
    gat_agg_kernel<<<NN, 128>>>(pH, pCSR, pROW, pES, pED, b3,
                                pXC, XCW, nullptr, nullptr, nullptr);

    // Pool + MLP head
    pool_kernel<<<dim3(XCW / 128, GG), 128>>>(pXC, batch, pPOOL);
    mlp1_kernel<<<dim3(HD / 128, GG / 4), 128>>>(pPOOL, mW1, mb1, pZ);
    bn_relu_kernel<<<HD, 64>>>(pZ, gam, bet);
    mlp2_kernel<<<1, GG * CC>>>(pZ, mW2, mb2, outp);
}